// round 1
// baseline (speedup 1.0000x reference)
#include <cuda_runtime.h>
#include <cstdint>
#include <math.h>

// Problem constants
#define Bd 8
#define Ld 32
#define Nd 256
#define Md 256
// rows of LSTM batch = Bd*Nd = 2048

// ---------------- device scratch (allocation-free: __device__ globals) --------
__device__ __align__(16) float g_w[Nd * Nd];                    // softmax(-dis)
__device__ __align__(16) float g_F1t[1024 * 256];               // [j][d]
__device__ __align__(16) float g_F2t[1024 * 256];               // [j][d]
__device__ __align__(16) float g_biasz[1024];                   // b_ih + b_hh
__device__ __align__(16) float g_xproj[(size_t)Bd * Ld * Nd * 1024]; // 256 MB
__device__ __align__(16) float g_h0[2048 * 256];                // zeros (h_{-1})
__device__ __align__(16) float g_c[2048 * 256];                 // cell state
__device__ __align__(16) float g_temp[(size_t)Bd * Ld * Nd * Md]; // h history (B,L,N,M)
__device__ __align__(16) float g_proj[(size_t)Bd * Ld * Nd * Md];
__device__ double g_sum[256];
__device__ double g_ssum[256];
__device__ float g_q[256];
__device__ float g_r0[256];

// ---------------- helpers -----------------------------------------------------
__device__ __forceinline__ uint32_t f2tf(float f) {
    uint32_t u;
    asm("cvt.rna.tf32.f32 %0, %1;" : "=r"(u) : "f"(f));
    return u;
}

__device__ __forceinline__ void mma_tf32(float* d, const uint32_t* a, const uint32_t* b) {
    asm volatile(
        "mma.sync.aligned.m16n8k8.row.col.f32.tf32.tf32.f32 "
        "{%0,%1,%2,%3}, {%4,%5,%6,%7}, {%8,%9}, {%0,%1,%2,%3};\n"
        : "+f"(d[0]), "+f"(d[1]), "+f"(d[2]), "+f"(d[3])
        : "r"(a[0]), "r"(a[1]), "r"(a[2]), "r"(a[3]), "r"(b[0]), "r"(b[1]));
}

__device__ __forceinline__ float sigf(float x) { return 1.f / (1.f + expf(-x)); }

// ---------------- init: zero states, bias, stats accumulators ----------------
__global__ void k_init(const float* __restrict__ bih, const float* __restrict__ bhh) {
    int idx = blockIdx.x * 256 + threadIdx.x;  // grid 2048 -> 524288 threads
    g_h0[idx] = 0.f;
    g_c[idx] = 0.f;
    if (idx < 1024) g_biasz[idx] = bih[idx] + bhh[idx];
    if (idx < 256) { g_sum[idx] = 0.0; g_ssum[idx] = 0.0; }
}

// ---------------- softmax of -dis, row-wise -----------------------------------
__global__ void k_softmax(const float* __restrict__ dis) {
    __shared__ float red[256];
    int o = blockIdx.x, t = threadIdx.x;
    float e = expf(-dis[o * 256 + t]);
    red[t] = e;
    __syncthreads();
    for (int s = 128; s > 0; s >>= 1) {
        if (t < s) red[t] += red[t + s];
        __syncthreads();
    }
    g_w[o * 256 + t] = e / red[0];
}

// ---------------- generic 128x128 tf32 GEMM: C = A @ Bt^T (+bias, +affine) ----
// A row-major [M x K], Bt row-major [N x K] (i.e. "col" operand), C row-major.
// AFA: A elem <- q[k]*A + r0[k];  AFB: same on Bt;  HB: add bias[col].
template <int AFA, int AFB, int HB>
__global__ void __launch_bounds__(256) k_gemm128(
    const float* __restrict__ A, long sA, int lda,
    const float* __restrict__ Bt, long sB, int ldb,
    float* __restrict__ C, long sC, int ldc,
    const float* __restrict__ bias,
    const float* __restrict__ qv, const float* __restrict__ rv, int K) {
    __shared__ uint32_t As[128 * 36];
    __shared__ uint32_t Bs[128 * 36];
    __shared__ float qs[256], rs[256];

    const int tid = threadIdx.x;
    const int z = blockIdx.z;
    A += sA * z; Bt += sB * z; C += sC * z;
    const int row0 = blockIdx.x * 128, col0 = blockIdx.y * 128;

    if (AFA || AFB) {
        for (int i = tid; i < K; i += 256) { qs[i] = qv[i]; rs[i] = rv[i]; }
        __syncthreads();
    }

    float acc[4][4][4] = {};
    const int lane = tid & 31, wid = tid >> 5;
    const int wm = (wid >> 2) * 64, wn = (wid & 3) * 32;
    const int g = lane >> 2, tq = lane & 3;
    const int rA = tid >> 3, c4 = (tid & 7) * 4;

    for (int k0 = 0; k0 < K; k0 += 32) {
#pragma unroll
        for (int i = 0; i < 4; i++) {
            int r = rA + i * 32;
            float4 v = *(const float4*)(A + (long)(row0 + r) * lda + k0 + c4);
            if (AFA) {
                int kk = k0 + c4;
                v.x = v.x * qs[kk] + rs[kk];     v.y = v.y * qs[kk + 1] + rs[kk + 1];
                v.z = v.z * qs[kk + 2] + rs[kk + 2]; v.w = v.w * qs[kk + 3] + rs[kk + 3];
            }
            uint4 u; u.x = f2tf(v.x); u.y = f2tf(v.y); u.z = f2tf(v.z); u.w = f2tf(v.w);
            *(uint4*)&As[r * 36 + c4] = u;
        }
#pragma unroll
        for (int i = 0; i < 4; i++) {
            int r = rA + i * 32;
            float4 v = *(const float4*)(Bt + (long)(col0 + r) * ldb + k0 + c4);
            if (AFB) {
                int kk = k0 + c4;
                v.x = v.x * qs[kk] + rs[kk];     v.y = v.y * qs[kk + 1] + rs[kk + 1];
                v.z = v.z * qs[kk + 2] + rs[kk + 2]; v.w = v.w * qs[kk + 3] + rs[kk + 3];
            }
            uint4 u; u.x = f2tf(v.x); u.y = f2tf(v.y); u.z = f2tf(v.z); u.w = f2tf(v.w);
            *(uint4*)&Bs[r * 36 + c4] = u;
        }
        __syncthreads();
#pragma unroll
        for (int kk = 0; kk < 32; kk += 8) {
            uint32_t af[4][4], bf[4][2];
#pragma unroll
            for (int mi = 0; mi < 4; mi++) {
                const uint32_t* p = &As[(wm + mi * 16 + g) * 36 + kk + tq];
                af[mi][0] = p[0]; af[mi][1] = p[36 * 8]; af[mi][2] = p[4]; af[mi][3] = p[36 * 8 + 4];
            }
#pragma unroll
            for (int ni = 0; ni < 4; ni++) {
                const uint32_t* p = &Bs[(wn + ni * 8 + g) * 36 + kk + tq];
                bf[ni][0] = p[0]; bf[ni][1] = p[4];
            }
#pragma unroll
            for (int mi = 0; mi < 4; mi++)
#pragma unroll
                for (int ni = 0; ni < 4; ni++) mma_tf32(acc[mi][ni], af[mi], bf[ni]);
        }
        __syncthreads();
    }
#pragma unroll
    for (int mi = 0; mi < 4; mi++) {
        int rr = row0 + wm + mi * 16 + g;
#pragma unroll
        for (int ni = 0; ni < 4; ni++) {
            int cc = col0 + wn + ni * 8 + tq * 2;
            float b0 = HB ? bias[cc] : 0.f, b1 = HB ? bias[cc + 1] : 0.f;
            C[(long)rr * ldc + cc] = acc[mi][ni][0] + b0;
            C[(long)rr * ldc + cc + 1] = acc[mi][ni][1] + b1;
            C[(long)(rr + 8) * ldc + cc] = acc[mi][ni][2] + b0;
            C[(long)(rr + 8) * ldc + cc + 1] = acc[mi][ni][3] + b1;
        }
    }
}

// ---------------- Xproj: per (b,l): X@F1t^T + (X*w)@F2t^T + biasz -------------
__global__ void __launch_bounds__(256) k_xproj(const float* __restrict__ X) {
    extern __shared__ uint32_t sm[];
    uint32_t* As1 = sm;
    uint32_t* As2 = sm + 128 * 36;
    uint32_t* Bs1 = sm + 2 * 128 * 36;
    uint32_t* Bs2 = sm + 3 * 128 * 36;

    const int tid = threadIdx.x;
    const int z = blockIdx.z;  // (b,l)
    const int row0 = blockIdx.x * 128, col0 = blockIdx.y * 128;
    const float* Xb = X + (long)z * 65536;

    float acc[4][4][4] = {};
    const int lane = tid & 31, wid = tid >> 5;
    const int wm = (wid >> 2) * 64, wn = (wid & 3) * 32;
    const int g = lane >> 2, tq = lane & 3;
    const int rA = tid >> 3, c4 = (tid & 7) * 4;

    for (int k0 = 0; k0 < 256; k0 += 32) {
#pragma unroll
        for (int i = 0; i < 4; i++) {
            int r = rA + i * 32;
            float4 xv = *(const float4*)(Xb + (long)(row0 + r) * 256 + k0 + c4);
            float4 wv = *(const float4*)(g_w + (row0 + r) * 256 + k0 + c4);
            uint4 u1; u1.x = f2tf(xv.x); u1.y = f2tf(xv.y); u1.z = f2tf(xv.z); u1.w = f2tf(xv.w);
            *(uint4*)&As1[r * 36 + c4] = u1;
            uint4 u2; u2.x = f2tf(xv.x * wv.x); u2.y = f2tf(xv.y * wv.y);
            u2.z = f2tf(xv.z * wv.z); u2.w = f2tf(xv.w * wv.w);
            *(uint4*)&As2[r * 36 + c4] = u2;
            float4 b1 = *(const float4*)(g_F1t + (long)(col0 + r) * 256 + k0 + c4);
            uint4 v1; v1.x = f2tf(b1.x); v1.y = f2tf(b1.y); v1.z = f2tf(b1.z); v1.w = f2tf(b1.w);
            *(uint4*)&Bs1[r * 36 + c4] = v1;
            float4 b2 = *(const float4*)(g_F2t + (long)(col0 + r) * 256 + k0 + c4);
            uint4 v2; v2.x = f2tf(b2.x); v2.y = f2tf(b2.y); v2.z = f2tf(b2.z); v2.w = f2tf(b2.w);
            *(uint4*)&Bs2[r * 36 + c4] = v2;
        }
        __syncthreads();
#pragma unroll
        for (int kk = 0; kk < 32; kk += 8) {
            uint32_t af[4][4], bf1[4][2], bf2[4][2];
#pragma unroll
            for (int ni = 0; ni < 4; ni++) {
                const uint32_t* p1 = &Bs1[(wn + ni * 8 + g) * 36 + kk + tq];
                bf1[ni][0] = p1[0]; bf1[ni][1] = p1[4];
                const uint32_t* p2 = &Bs2[(wn + ni * 8 + g) * 36 + kk + tq];
                bf2[ni][0] = p2[0]; bf2[ni][1] = p2[4];
            }
#pragma unroll
            for (int mi = 0; mi < 4; mi++) {
                const uint32_t* p = &As1[(wm + mi * 16 + g) * 36 + kk + tq];
                af[mi][0] = p[0]; af[mi][1] = p[36 * 8]; af[mi][2] = p[4]; af[mi][3] = p[36 * 8 + 4];
            }
#pragma unroll
            for (int mi = 0; mi < 4; mi++)
#pragma unroll
                for (int ni = 0; ni < 4; ni++) mma_tf32(acc[mi][ni], af[mi], bf1[ni]);
#pragma unroll
            for (int mi = 0; mi < 4; mi++) {
                const uint32_t* p = &As2[(wm + mi * 16 + g) * 36 + kk + tq];
                af[mi][0] = p[0]; af[mi][1] = p[36 * 8]; af[mi][2] = p[4]; af[mi][3] = p[36 * 8 + 4];
            }
#pragma unroll
            for (int mi = 0; mi < 4; mi++)
#pragma unroll
                for (int ni = 0; ni < 4; ni++) mma_tf32(acc[mi][ni], af[mi], bf2[ni]);
        }
        __syncthreads();
    }
#pragma unroll
    for (int mi = 0; mi < 4; mi++) {
        int rr = row0 + wm + mi * 16 + g;
#pragma unroll
        for (int ni = 0; ni < 4; ni++) {
            int cc = col0 + wn + ni * 8 + tq * 2;
            float b0 = g_biasz[cc], b1 = g_biasz[cc + 1];
            float* Cp = g_xproj + ((long)z * 256 + rr) * 1024 + cc;
            Cp[0] = acc[mi][ni][0] + b0;
            Cp[1] = acc[mi][ni][1] + b1;
            Cp[1024] = acc[mi][ni][2] + b0;  // row rr+8 -> +8*1024; see below
            Cp[1025] = acc[mi][ni][3] + b1;
        }
    }
}

// NOTE on k_xproj epilogue above: rows rr and rr+8 -> offset 8*1024 floats.
// (fixed below by a corrected epilogue; see k_xproj_fix guard) -- instead we
// inline the correct arithmetic here via a compile-time constant:
// Cp[1024] would be rr+1 which is WRONG; the correct stores are issued in the
// epilogue of the real kernel below. To keep a single kernel, the epilogue above
// is dead code only if this comment lied — it does not. We must fix it:
// (The actual fix: the two bottom stores use +8*1024.)
// To guarantee correctness we re-declare the kernel with the right epilogue and
// use only that one.

__global__ void __launch_bounds__(256) k_xproj2(const float* __restrict__ X) {
    extern __shared__ uint32_t sm[];
    uint32_t* As1 = sm;
    uint32_t* As2 = sm + 128 * 36;
    uint32_t* Bs1 = sm + 2 * 128 * 36;
    uint32_t* Bs2 = sm + 3 * 128 * 36;

    const int tid = threadIdx.x;
    const int z = blockIdx.z;
    const int row0 = blockIdx.x * 128, col0 = blockIdx.y * 128;
    const float* Xb = X + (long)z * 65536;

    float acc[4][4][4] = {};
    const int lane = tid & 31, wid = tid >> 5;
    const int wm = (wid >> 2) * 64, wn = (wid & 3) * 32;
    const int g = lane >> 2, tq = lane & 3;
    const int rA = tid >> 3, c4 = (tid & 7) * 4;

    for (int k0 = 0; k0 < 256; k0 += 32) {
#pragma unroll
        for (int i = 0; i < 4; i++) {
            int r = rA + i * 32;
            float4 xv = *(const float4*)(Xb + (long)(row0 + r) * 256 + k0 + c4);
            float4 wv = *(const float4*)(g_w + (row0 + r) * 256 + k0 + c4);
            uint4 u1; u1.x = f2tf(xv.x); u1.y = f2tf(xv.y); u1.z = f2tf(xv.z); u1.w = f2tf(xv.w);
            *(uint4*)&As1[r * 36 + c4] = u1;
            uint4 u2; u2.x = f2tf(xv.x * wv.x); u2.y = f2tf(xv.y * wv.y);
            u2.z = f2tf(xv.z * wv.z); u2.w = f2tf(xv.w * wv.w);
            *(uint4*)&As2[r * 36 + c4] = u2;
            float4 b1 = *(const float4*)(g_F1t + (long)(col0 + r) * 256 + k0 + c4);
            uint4 v1; v1.x = f2tf(b1.x); v1.y = f2tf(b1.y); v1.z = f2tf(b1.z); v1.w = f2tf(b1.w);
            *(uint4*)&Bs1[r * 36 + c4] = v1;
            float4 b2 = *(const float4*)(g_F2t + (long)(col0 + r) * 256 + k0 + c4);
            uint4 v2; v2.x = f2tf(b2.x); v2.y = f2tf(b2.y); v2.z = f2tf(b2.z); v2.w = f2tf(b2.w);
            *(uint4*)&Bs2[r * 36 + c4] = v2;
        }
        __syncthreads();
#pragma unroll
        for (int kk = 0; kk < 32; kk += 8) {
            uint32_t af[4][4], bf1[4][2], bf2[4][2];
#pragma unroll
            for (int ni = 0; ni < 4; ni++) {
                const uint32_t* p1 = &Bs1[(wn + ni * 8 + g) * 36 + kk + tq];
                bf1[ni][0] = p1[0]; bf1[ni][1] = p1[4];
                const uint32_t* p2 = &Bs2[(wn + ni * 8 + g) * 36 + kk + tq];
                bf2[ni][0] = p2[0]; bf2[ni][1] = p2[4];
            }
#pragma unroll
            for (int mi = 0; mi < 4; mi++) {
                const uint32_t* p = &As1[(wm + mi * 16 + g) * 36 + kk + tq];
                af[mi][0] = p[0]; af[mi][1] = p[36 * 8]; af[mi][2] = p[4]; af[mi][3] = p[36 * 8 + 4];
            }
#pragma unroll
            for (int mi = 0; mi < 4; mi++)
#pragma unroll
                for (int ni = 0; ni < 4; ni++) mma_tf32(acc[mi][ni], af[mi], bf1[ni]);
#pragma unroll
            for (int mi = 0; mi < 4; mi++) {
                const uint32_t* p = &As2[(wm + mi * 16 + g) * 36 + kk + tq];
                af[mi][0] = p[0]; af[mi][1] = p[36 * 8]; af[mi][2] = p[4]; af[mi][3] = p[36 * 8 + 4];
            }
#pragma unroll
            for (int mi = 0; mi < 4; mi++)
#pragma unroll
                for (int ni = 0; ni < 4; ni++) mma_tf32(acc[mi][ni], af[mi], bf2[ni]);
        }
        __syncthreads();
    }
#pragma unroll
    for (int mi = 0; mi < 4; mi++) {
        int rr = row0 + wm + mi * 16 + g;
#pragma unroll
        for (int ni = 0; ni < 4; ni++) {
            int cc = col0 + wn + ni * 8 + tq * 2;
            float b0 = g_biasz[cc], b1 = g_biasz[cc + 1];
            float* Cp = g_xproj + ((long)z * 256 + rr) * 1024 + cc;
            Cp[0] = acc[mi][ni][0] + b0;
            Cp[1] = acc[mi][ni][1] + b1;
            Cp[8 * 1024] = acc[mi][ni][2] + b0;
            Cp[8 * 1024 + 1] = acc[mi][ni][3] + b1;
        }
    }
}

// ---------------- fused LSTM step: Z = h@Whh^T (gathered 4 gates) + gates -----
// block: 64 rows x (4 gates x 64 m); grid (32, 4)
__global__ void __launch_bounds__(256) k_lstm_step(int t, const float* __restrict__ Whh) {
    extern __shared__ uint32_t sm[];
    uint32_t* As = sm;                 // 64*36
    uint32_t* Bs = sm + 64 * 36;       // 256*36
    float* Zs = (float*)sm;            // 64*260 (aliases; used after GEMM)

    const int tid = threadIdx.x;
    const int rows0 = blockIdx.x * 64;
    const int m0 = blockIdx.y * 64;
    const int b = rows0 >> 8;
    const int n0 = rows0 & 255;
    const float* Ab = (t == 0)
        ? (g_h0 + (long)rows0 * 256)
        : (g_temp + (((long)b * Ld + (t - 1)) * 256 + n0) * 256);

    float acc[2][8][4] = {};
    const int lane = tid & 31, wid = tid >> 5;
    const int wm = (wid >> 2) * 32, wn = (wid & 3) * 64;
    const int g = lane >> 2, tq = lane & 3;
    const int rA = tid >> 3, c4 = (tid & 7) * 4;

    for (int k0 = 0; k0 < 256; k0 += 32) {
#pragma unroll
        for (int i = 0; i < 2; i++) {
            int r = rA + i * 32;
            float4 v = *(const float4*)(Ab + (long)r * 256 + k0 + c4);
            uint4 u; u.x = f2tf(v.x); u.y = f2tf(v.y); u.z = f2tf(v.z); u.w = f2tf(v.w);
            *(uint4*)&As[r * 36 + c4] = u;
        }
#pragma unroll
        for (int i = 0; i < 8; i++) {
            int ng = rA + i * 32;
            int wrow = (ng >> 6) * 256 + m0 + (ng & 63);
            float4 v = *(const float4*)(Whh + (long)wrow * 256 + k0 + c4);
            uint4 u; u.x = f2tf(v.x); u.y = f2tf(v.y); u.z = f2tf(v.z); u.w = f2tf(v.w);
            *(uint4*)&Bs[ng * 36 + c4] = u;
        }
        __syncthreads();
#pragma unroll
        for (int kk = 0; kk < 32; kk += 8) {
            uint32_t af[2][4], bf[8][2];
#pragma unroll
            for (int mi = 0; mi < 2; mi++) {
                const uint32_t* p = &As[(wm + mi * 16 + g) * 36 + kk + tq];
                af[mi][0] = p[0]; af[mi][1] = p[36 * 8]; af[mi][2] = p[4]; af[mi][3] = p[36 * 8 + 4];
            }
#pragma unroll
            for (int ni = 0; ni < 8; ni++) {
                const uint32_t* p = &Bs[(wn + ni * 8 + g) * 36 + kk + tq];
                bf[ni][0] = p[0]; bf[ni][1] = p[4];
            }
#pragma unroll
            for (int mi = 0; mi < 2; mi++)
#pragma unroll
                for (int ni = 0; ni < 8; ni++) mma_tf32(acc[mi][ni], af[mi], bf[ni]);
        }
        __syncthreads();
    }
    // stage Z in shared
#pragma unroll
    for (int mi = 0; mi < 2; mi++) {
        int zr = wm + mi * 16 + g;
#pragma unroll
        for (int ni = 0; ni < 8; ni++) {
            int zc = wn + ni * 8 + tq * 2;
            Zs[zr * 260 + zc] = acc[mi][ni][0];
            Zs[zr * 260 + zc + 1] = acc[mi][ni][1];
            Zs[(zr + 8) * 260 + zc] = acc[mi][ni][2];
            Zs[(zr + 8) * 260 + zc + 1] = acc[mi][ni][3];
        }
    }
    __syncthreads();

    // gates + state update: thread handles m = tid%64, rows (tid/64)*16..+15
    const int ml = tid & 63;
    const int rg = tid >> 6;
#pragma unroll 4
    for (int i = 0; i < 16; i++) {
        int r = rg * 16 + i;
        int rowg = rows0 + r;
        int nn = rowg & 255;
        int mg = m0 + ml;
        long xbase = (((long)b * Ld + t) * 256 + nn) * 1024;
        float zi = Zs[r * 260 + ml] + g_xproj[xbase + mg];
        float zf = Zs[r * 260 + 64 + ml] + g_xproj[xbase + 256 + mg];
        float zg = Zs[r * 260 + 128 + ml] + g_xproj[xbase + 512 + mg];
        float zo = Zs[r * 260 + 192 + ml] + g_xproj[xbase + 768 + mg];
        float ig = sigf(zi), fg = sigf(zf), gg = tanhf(zg), og = sigf(zo);
        long cidx = (long)rowg * 256 + mg;
        float c = fg * g_c[cidx] + ig * gg;
        g_c[cidx] = c;
        float h = og * tanhf(c);
        g_temp[(((long)b * Ld + t) * 256 + nn) * 256 + mg] = h;
    }
}

// ---------------- BN stats ----------------------------------------------------
__global__ void k_stats() {
    int m = threadIdx.x;
    long base = (long)blockIdx.x * 256 * 256;
    float s = 0.f, ss = 0.f;
#pragma unroll 4
    for (int j = 0; j < 256; j++) {
        float v = g_temp[base + (long)j * 256 + m];
        s += v; ss += v * v;
    }
    atomicAdd(&g_sum[m], (double)s);
    atomicAdd(&g_ssum[m], (double)ss);
}

__global__ void k_finalize(const float* __restrict__ gamma, const float* __restrict__ beta) {
    int m = threadIdx.x;
    double mu = g_sum[m] / 65536.0;
    double var = g_ssum[m] / 65536.0 - mu * mu;
    float q = gamma[m] * (float)(1.0 / sqrt(var + 1e-5));
    g_q[m] = q;
    g_r0[m] = beta[m] - (float)mu * q;
}

// ---------------- launch ------------------------------------------------------
extern "C" void kernel_launch(void* const* d_in, const int* in_sizes, int n_in,
                              void* d_out, int out_size) {
    const float* X     = (const float*)d_in[0];
    const float* dis   = (const float*)d_in[1];
    const float* E1    = (const float*)d_in[2];
    const float* E2    = (const float*)d_in[3];
    const float* W_ih  = (const float*)d_in[4];
    const float* W_hh  = (const float*)d_in[5];
    const float* b_ih  = (const float*)d_in[6];
    const float* b_hh  = (const float*)d_in[7];
    const float* gamma = (const float*)d_in[8];
    const float* beta  = (const float*)d_in[9];
    const float* W_lin = (const float*)d_in[10];
    const float* b_lin = (const float*)d_in[11];
    float* out = (float*)d_out;

    cudaFuncSetAttribute(k_xproj2, cudaFuncAttributeMaxDynamicSharedMemorySize, 4 * 128 * 36 * 4);
    cudaFuncSetAttribute(k_lstm_step, cudaFuncAttributeMaxDynamicSharedMemorySize, 64 * 260 * 4);

    float *pF1t, *pF2t, *pTemp, *pProj, *pQ, *pR0;
    cudaGetSymbolAddress((void**)&pF1t, g_F1t);
    cudaGetSymbolAddress((void**)&pF2t, g_F2t);
    cudaGetSymbolAddress((void**)&pTemp, g_temp);
    cudaGetSymbolAddress((void**)&pProj, g_proj);
    cudaGetSymbolAddress((void**)&pQ, g_q);
    cudaGetSymbolAddress((void**)&pR0, g_r0);

    k_init<<<2048, 256>>>(b_ih, b_hh);
    k_softmax<<<256, 256>>>(dis);

    // F1t[j,d] = sum_m W_ih[j,m]*E1[d,m] ; F2t uses W_ih cols [256,512) and E2
    k_gemm128<0, 0, 0><<<dim3(8, 2, 1), 256>>>(W_ih, 0, 512, E1, 0, 256,
                                               pF1t, 0, 256, nullptr, nullptr, nullptr, 256);
    k_gemm128<0, 0, 0><<<dim3(8, 2, 1), 256>>>(W_ih + 256, 0, 512, E2, 0, 256,
                                               pF2t, 0, 256, nullptr, nullptr, nullptr, 256);

    k_xproj2<<<dim3(2, 8, 256), 256, 4 * 128 * 36 * 4>>>(X);

    for (int t = 0; t < Ld; t++)
        k_lstm_step<<<dim3(32, 4, 1), 256, 64 * 260 * 4>>>(t, W_hh);

    k_stats<<<256, 256>>>();
    k_finalize<<<1, 256>>>(gamma, beta);

    // proj = affine(temp) @ W_lin^T + b_lin       (per (b,l))
    k_gemm128<1, 0, 1><<<dim3(2, 2, 256), 256>>>(pTemp, 65536, 256, W_lin, 0, 256,
                                                 pProj, 65536, 256, b_lin, pQ, pR0, 256);
    // out = proj @ affine(temp)^T                  (per (b,l))
    k_gemm128<0, 1, 0><<<dim3(2, 2, 256), 256>>>(pProj, 65536, 256, pTemp, 65536, 256,
                                                 out, 65536, 256, nullptr, pQ, pR0, 256);
}

// round 2
// speedup vs baseline: 1.3073x; 1.3073x over previous
#include <cuda_runtime.h>
#include <cstdint>
#include <math.h>

#define Bd 8
#define Ld 32

// ---------------- device scratch ------------------------------------------
__device__ __align__(16) float g_w[256 * 256];
__device__ __align__(16) float g_Xw[(size_t)Bd * Ld * 256 * 256];
__device__ __align__(16) float g_Ecat[2 * 256 * 256];
__device__ __align__(16) float g_Fcat[1024 * 512];
__device__ __align__(16) float g_biasz[1024];
__device__ __align__(16) float g_xproj[(size_t)Bd * Ld * 256 * 1024];
__device__ __align__(16) float g_temp[(size_t)Bd * Ld * 256 * 256];
__device__ __align__(16) float g_proj[(size_t)Bd * Ld * 256 * 256];
__device__ double g_sum[256], g_ssum[256];
__device__ float g_q[256], g_r0[256];
__device__ unsigned g_barcnt;
__device__ volatile unsigned g_bargen;

// ---------------- helpers --------------------------------------------------
__device__ __forceinline__ uint32_t f2tf(float f) {
    uint32_t u;
    asm("cvt.rna.tf32.f32 %0, %1;" : "=r"(u) : "f"(f));
    return u;
}
__device__ __forceinline__ void mma_tf32(float* d, const uint32_t* a, const uint32_t* b) {
    asm volatile(
        "mma.sync.aligned.m16n8k8.row.col.f32.tf32.tf32.f32 "
        "{%0,%1,%2,%3}, {%4,%5,%6,%7}, {%8,%9}, {%0,%1,%2,%3};\n"
        : "+f"(d[0]), "+f"(d[1]), "+f"(d[2]), "+f"(d[3])
        : "r"(a[0]), "r"(a[1]), "r"(a[2]), "r"(a[3]), "r"(b[0]), "r"(b[1]));
}
__device__ __forceinline__ float sigf(float x) { return 1.f / (1.f + expf(-x)); }

__device__ __forceinline__ void cp16(uint32_t s, const void* g) {
    asm volatile("cp.async.cg.shared.global [%0], [%1], 16;" :: "r"(s), "l"(g));
}
#define CPCOMMIT asm volatile("cp.async.commit_group;")
#define CPWAIT1 asm volatile("cp.async.wait_group 1;")
#define CPWAIT0 asm volatile("cp.async.wait_group 0;")

// ---------------- init ------------------------------------------------------
__global__ void k_init(const float* __restrict__ bih, const float* __restrict__ bhh) {
    int i = blockIdx.x * 256 + threadIdx.x;  // grid 4
    g_biasz[i] = bih[i] + bhh[i];
    if (i < 256) { g_sum[i] = 0.0; g_ssum[i] = 0.0; }
    if (i == 0) { g_barcnt = 0; g_bargen = 0; }
}

// ---------------- softmax of -dis, row-wise ---------------------------------
__global__ void k_softmax(const float* __restrict__ dis) {
    __shared__ float red[256];
    int o = blockIdx.x, t = threadIdx.x;
    float e = expf(-dis[o * 256 + t]);
    red[t] = e;
    __syncthreads();
    for (int s = 128; s > 0; s >>= 1) {
        if (t < s) red[t] += red[t + s];
        __syncthreads();
    }
    g_w[o * 256 + t] = e / red[0];
}

// ---------------- prep: Xw = X * w (broadcast over b,l); Ecat copies --------
__global__ void k_prep(const float* __restrict__ X, const float* __restrict__ E1,
                       const float* __restrict__ E2) {
    long i = (long)blockIdx.x * 256 + threadIdx.x;  // grid 65536
    int nd = (int)(i & 65535);
    g_Xw[i] = X[i] * g_w[nd];
    if (i < 65536) g_Ecat[i] = E1[i];
    else if (i < 131072) g_Ecat[i] = E2[i - 65536];
}

// ---------------- generic 128x128 tf32 GEMM, cp.async double-buffered -------
// C = A' @ Bt^T (+bias). A' row-major [.,lda]; for AHALF, k>=256 reads A2.
// AMODE==1: A elem <- q[k]*A + r0[k] ;  BMODE==1: same on Bt. k-dim affine.
template <int AMODE, int BMODE, int AHALF, int HB>
__global__ void __launch_bounds__(256, 2) kg(
    const float* __restrict__ A, const float* __restrict__ A2, long sA, int lda,
    const float* __restrict__ Bt, long sB, int ldb,
    float* __restrict__ C, long sC, int ldc,
    const float* __restrict__ bias,
    const float* __restrict__ qv, const float* __restrict__ rv, int K) {
    extern __shared__ float sm[];
    float* As = sm;                  // 2 * 128*36
    float* Bs = sm + 2 * 128 * 36;   // 2 * 128*36
    __shared__ float qs[256], rs[256];

    const int tid = threadIdx.x;
    const int z = blockIdx.z;
    const float* Ab = A + sA * z;
    const float* Ab2 = AHALF ? (A2 + sA * z) : nullptr;
    const float* Bb = Bt + sB * z;
    float* Cb = C + sC * z;
    const int row0 = blockIdx.x * 128, col0 = blockIdx.y * 128;

    if (AMODE == 1 || BMODE == 1) {
        for (int i = tid; i < 256; i += 256) { qs[i] = qv[i]; rs[i] = rv[i]; }
        __syncthreads();
    }

    const int lane = tid & 31, wid = tid >> 5;
    const int wm = (wid >> 2) * 64, wn = (wid & 3) * 32;
    const int g = lane >> 2, tq = lane & 3;
    const int rA = tid >> 3, c4 = (tid & 7) * 4;
    const int nk = K / 32;

    // loader
    auto load = [&](int stg, int k0) {
        const float* Asrc;
        int kc;
        if (AHALF && k0 >= 256) { Asrc = Ab2; kc = k0 - 256 + c4; }
        else { Asrc = Ab; kc = k0 + c4; }
        uint32_t ab = (uint32_t)__cvta_generic_to_shared(As + stg * 128 * 36);
        uint32_t bb = (uint32_t)__cvta_generic_to_shared(Bs + stg * 128 * 36);
#pragma unroll
        for (int i = 0; i < 4; i++) {
            int r = rA + i * 32;
            cp16(ab + (r * 36 + c4) * 4, Asrc + (long)(row0 + r) * lda + kc);
        }
#pragma unroll
        for (int i = 0; i < 4; i++) {
            int r = rA + i * 32;
            cp16(bb + (r * 36 + c4) * 4, Bb + (long)(col0 + r) * ldb + k0 + c4);
        }
        CPCOMMIT;
    };

    float acc[4][4][4] = {};
    load(0, 0);
    for (int kt = 0; kt < nk; kt++) {
        if (kt + 1 < nk) { load((kt + 1) & 1, (kt + 1) * 32); CPWAIT1; }
        else { CPWAIT0; }
        __syncthreads();
        const float* as = As + (kt & 1) * 128 * 36;
        const float* bs = Bs + (kt & 1) * 128 * 36;
        const int k0 = kt * 32;
#pragma unroll
        for (int kk = 0; kk < 32; kk += 8) {
            uint32_t af[4][4], bf[4][2];
            const int kA = k0 + kk + tq;
#pragma unroll
            for (int mi = 0; mi < 4; mi++) {
                const float* p = &as[(wm + mi * 16 + g) * 36 + kk + tq];
                float a0 = p[0], a1 = p[36 * 8], a2 = p[4], a3 = p[36 * 8 + 4];
                if (AMODE == 1) {
                    a0 = a0 * qs[kA] + rs[kA];       a1 = a1 * qs[kA] + rs[kA];
                    a2 = a2 * qs[kA + 4] + rs[kA + 4]; a3 = a3 * qs[kA + 4] + rs[kA + 4];
                }
                af[mi][0] = f2tf(a0); af[mi][1] = f2tf(a1);
                af[mi][2] = f2tf(a2); af[mi][3] = f2tf(a3);
            }
#pragma unroll
            for (int ni = 0; ni < 4; ni++) {
                const float* p = &bs[(wn + ni * 8 + g) * 36 + kk + tq];
                float b0 = p[0], b1 = p[4];
                if (BMODE == 1) {
                    b0 = b0 * qs[kA] + rs[kA];
                    b1 = b1 * qs[kA + 4] + rs[kA + 4];
                }
                bf[ni][0] = f2tf(b0); bf[ni][1] = f2tf(b1);
            }
#pragma unroll
            for (int mi = 0; mi < 4; mi++)
#pragma unroll
                for (int ni = 0; ni < 4; ni++) mma_tf32(acc[mi][ni], af[mi], bf[ni]);
        }
        __syncthreads();
    }
#pragma unroll
    for (int mi = 0; mi < 4; mi++) {
        int rr = row0 + wm + mi * 16 + g;
#pragma unroll
        for (int ni = 0; ni < 4; ni++) {
            int cc = col0 + wn + ni * 8 + tq * 2;
            float b0 = HB ? bias[cc] : 0.f, b1 = HB ? bias[cc + 1] : 0.f;
            Cb[(long)rr * ldc + cc] = acc[mi][ni][0] + b0;
            Cb[(long)rr * ldc + cc + 1] = acc[mi][ni][1] + b1;
            Cb[(long)(rr + 8) * ldc + cc] = acc[mi][ni][2] + b0;
            Cb[(long)(rr + 8) * ldc + cc + 1] = acc[mi][ni][3] + b1;
        }
    }
}

// ---------------- grid barrier ----------------------------------------------
__device__ __forceinline__ void gridbar(unsigned nb, unsigned& mygen) {
    __syncthreads();
    if (threadIdx.x == 0) {
        __threadfence();
        unsigned old = atomicAdd(&g_barcnt, 1u);
        if (old == nb - 1) {
            g_barcnt = 0;
            __threadfence();
            atomicAdd((unsigned*)&g_bargen, 1u);
        } else {
            while (g_bargen <= mygen) {}
        }
        __threadfence();
    }
    __syncthreads();
    mygen++;
}

// ---------------- persistent fused LSTM --------------------------------------
// grid 128 blocks (32 row-tiles of 64 x 4 m-tiles of 64 gate cols), 256 thr.
// Per step: Z = h_{t-1} @ Whh^T (gathered 4-gate cols), gates from Z + xproj,
// c kept in registers, h -> g_temp; BN stats folded in.
__global__ void __launch_bounds__(256, 1) k_lstm(const float* __restrict__ Whh) {
    extern __shared__ float sm[];
    float* As = sm;                            // 2*64*36   = 4608 f
    float* Bs = sm + 2 * 64 * 36;              // 2*256*36  = 18432 f
    float* Zs = Bs + 2 * 256 * 36;             // 64*260    = 16640 f
    float* Xp = Zs + 64 * 260;                 // 64*256    = 16384 f

    const int tid = threadIdx.x;
    const int bid = blockIdx.x;
    const int rows0 = (bid >> 2) * 64, m0 = (bid & 3) * 64;
    const int b = rows0 >> 8, n0 = rows0 & 255;
    const int lane = tid & 31, wid = tid >> 5;
    const int wm = (wid >> 2) * 32, wn = (wid & 3) * 64;
    const int g = lane >> 2, tq = lane & 3;
    const int rA = tid >> 3, c4 = (tid & 7) * 4;
    const int ml = tid & 63, rg = tid >> 6;

    float creg[16];
#pragma unroll
    for (int i = 0; i < 16; i++) creg[i] = 0.f;
    double sd = 0.0, ssd = 0.0;
    unsigned mygen = 0;

    const uint32_t xb = (uint32_t)__cvta_generic_to_shared(Xp);

    for (int t = 0; t < Ld; t++) {
        const long xz = ((long)b * Ld + t) * 256;
        // prefetch xproj slice for this step into Xp (its own commit group)
        {
#pragma unroll
            for (int k = 0; k < 16; k++) {
                int c = tid + k * 256;
                int row = c >> 6;
                int col4 = (c & 63) * 4;
                int gate = col4 >> 6, mcol = col4 & 63;
                cp16(xb + (row * 256 + col4) * 4,
                     g_xproj + (xz + n0 + row) * 1024 + gate * 256 + m0 + mcol);
            }
            CPCOMMIT;
        }

        float acc[2][8][4] = {};
        if (t > 0) {
            const float* Ab = g_temp + (((long)b * Ld + (t - 1)) * 256 + n0) * 256;
            auto load = [&](int stg, int k0) {
                uint32_t ab = (uint32_t)__cvta_generic_to_shared(As + stg * 64 * 36);
                uint32_t bb = (uint32_t)__cvta_generic_to_shared(Bs + stg * 256 * 36);
#pragma unroll
                for (int i = 0; i < 2; i++) {
                    int r = rA + i * 32;
                    cp16(ab + (r * 36 + c4) * 4, Ab + (long)r * 256 + k0 + c4);
                }
#pragma unroll
                for (int i = 0; i < 8; i++) {
                    int ng = rA + i * 32;
                    int wrow = (ng >> 6) * 256 + m0 + (ng & 63);
                    cp16(bb + (ng * 36 + c4) * 4, Whh + (long)wrow * 256 + k0 + c4);
                }
                CPCOMMIT;
            };
            load(0, 0);
            for (int kt = 0; kt < 8; kt++) {
                if (kt < 7) { load((kt + 1) & 1, (kt + 1) * 32); CPWAIT1; }
                else { CPWAIT0; }
                __syncthreads();
                const float* as = As + (kt & 1) * 64 * 36;
                const float* bs = Bs + (kt & 1) * 256 * 36;
#pragma unroll
                for (int kk = 0; kk < 32; kk += 8) {
                    uint32_t af[2][4], bf[8][2];
#pragma unroll
                    for (int mi = 0; mi < 2; mi++) {
                        const float* p = &as[(wm + mi * 16 + g) * 36 + kk + tq];
                        af[mi][0] = f2tf(p[0]);      af[mi][1] = f2tf(p[36 * 8]);
                        af[mi][2] = f2tf(p[4]);      af[mi][3] = f2tf(p[36 * 8 + 4]);
                    }
#pragma unroll
                    for (int ni = 0; ni < 8; ni++) {
                        const float* p = &bs[(wn + ni * 8 + g) * 36 + kk + tq];
                        bf[ni][0] = f2tf(p[0]); bf[ni][1] = f2tf(p[4]);
                    }
#pragma unroll
                    for (int mi = 0; mi < 2; mi++)
#pragma unroll
                        for (int ni = 0; ni < 8; ni++) mma_tf32(acc[mi][ni], af[mi], bf[ni]);
                }
                __syncthreads();
            }
        } else {
            CPWAIT0;   // ensure Xp landed
            __syncthreads();
        }

        // stage Z in shared
#pragma unroll
        for (int mi = 0; mi < 2; mi++) {
            int zr = wm + mi * 16 + g;
#pragma unroll
            for (int ni = 0; ni < 8; ni++) {
                int zc = wn + ni * 8 + tq * 2;
                Zs[zr * 260 + zc] = acc[mi][ni][0];
                Zs[zr * 260 + zc + 1] = acc[mi][ni][1];
                Zs[(zr + 8) * 260 + zc] = acc[mi][ni][2];
                Zs[(zr + 8) * 260 + zc + 1] = acc[mi][ni][3];
            }
        }
        __syncthreads();

        // gates + state update (xproj from Xp smem)
        float ps = 0.f, pss = 0.f;
#pragma unroll 4
        for (int i = 0; i < 16; i++) {
            int r = rg * 16 + i;
            int nn = n0 + r;
            float zi = Zs[r * 260 + ml] + Xp[r * 256 + ml];
            float zf = Zs[r * 260 + 64 + ml] + Xp[r * 256 + 64 + ml];
            float zg = Zs[r * 260 + 128 + ml] + Xp[r * 256 + 128 + ml];
            float zo = Zs[r * 260 + 192 + ml] + Xp[r * 256 + 192 + ml];
            float ig = sigf(zi), fg = sigf(zf), gg = tanhf(zg), og = sigf(zo);
            float c = fg * creg[i] + ig * gg;
            creg[i] = c;
            float h = og * tanhf(c);
            g_temp[(xz + nn) * 256 + m0 + ml] = h;
            ps += h; pss += h * h;
        }
        sd += (double)ps; ssd += (double)pss;

        if (t < Ld - 1) gridbar(128, mygen);
    }
    atomicAdd(&g_sum[m0 + ml], sd);
    atomicAdd(&g_ssum[m0 + ml], ssd);
}

// ---------------- BN finalize -------------------------------------------------
__global__ void k_finalize(const float* __restrict__ gamma, const float* __restrict__ beta) {
    int m = threadIdx.x;
    double mu = g_sum[m] / 65536.0;
    double var = g_ssum[m] / 65536.0 - mu * mu;
    float q = gamma[m] * (float)(1.0 / sqrt(var + 1e-5));
    g_q[m] = q;
    g_r0[m] = beta[m] - (float)mu * q;
}

// ---------------- launch ------------------------------------------------------
extern "C" void kernel_launch(void* const* d_in, const int* in_sizes, int n_in,
                              void* d_out, int out_size) {
    const float* X     = (const float*)d_in[0];
    const float* dis   = (const float*)d_in[1];
    const float* E1    = (const float*)d_in[2];
    const float* E2    = (const float*)d_in[3];
    const float* W_ih  = (const float*)d_in[4];
    const float* W_hh  = (const float*)d_in[5];
    const float* b_ih  = (const float*)d_in[6];
    const float* b_hh  = (const float*)d_in[7];
    const float* gamma = (const float*)d_in[8];
    const float* beta  = (const float*)d_in[9];
    const float* W_lin = (const float*)d_in[10];
    const float* b_lin = (const float*)d_in[11];
    float* out = (float*)d_out;

    const int GSMEM = 2 * 2 * 128 * 36 * 4;         // 73728 B
    const int LSMEM = (2 * 64 * 36 + 2 * 256 * 36 + 64 * 260 + 64 * 256) * 4;

    cudaFuncSetAttribute(kg<0, 0, 0, 0>, cudaFuncAttributeMaxDynamicSharedMemorySize, GSMEM);
    cudaFuncSetAttribute(kg<0, 0, 1, 1>, cudaFuncAttributeMaxDynamicSharedMemorySize, GSMEM);
    cudaFuncSetAttribute(kg<1, 0, 0, 1>, cudaFuncAttributeMaxDynamicSharedMemorySize, GSMEM);
    cudaFuncSetAttribute(kg<0, 1, 0, 0>, cudaFuncAttributeMaxDynamicSharedMemorySize, GSMEM);
    cudaFuncSetAttribute(k_lstm, cudaFuncAttributeMaxDynamicSharedMemorySize, LSMEM);

    float *pXw, *pEcat, *pFcat, *pBiasz, *pXproj, *pTemp, *pProj, *pQ, *pR0;
    cudaGetSymbolAddress((void**)&pXw, g_Xw);
    cudaGetSymbolAddress((void**)&pEcat, g_Ecat);
    cudaGetSymbolAddress((void**)&pFcat, g_Fcat);
    cudaGetSymbolAddress((void**)&pBiasz, g_biasz);
    cudaGetSymbolAddress((void**)&pXproj, g_xproj);
    cudaGetSymbolAddress((void**)&pTemp, g_temp);
    cudaGetSymbolAddress((void**)&pProj, g_proj);
    cudaGetSymbolAddress((void**)&pQ, g_q);
    cudaGetSymbolAddress((void**)&pR0, g_r0);

    k_init<<<4, 256>>>(b_ih, b_hh);
    k_softmax<<<256, 256>>>(dis);
    k_prep<<<65536, 256>>>(X, E1, E2);

    // Fcat[j, 0:256] = W_ih[:, 0:256] @ E1^T ; Fcat[j, 256:512] = W_ih[:,256:512] @ E2^T
    kg<0, 0, 0, 0><<<dim3(8, 2, 2), 256, GSMEM>>>(
        W_ih, nullptr, 256, 512, pEcat, 65536, 256,
        pFcat, 256, 512, nullptr, nullptr, nullptr, 256);

    // xproj = [X | Xw] @ Fcat^T + biasz  (K=512), per (b,l)
    kg<0, 0, 1, 1><<<dim3(2, 8, 256), 256, GSMEM>>>(
        X, pXw, 65536, 256, pFcat, 0, 512,
        pXproj, 262144, 1024, pBiasz, nullptr, nullptr, 512);

    // persistent LSTM over 32 steps (+BN stats)
    k_lstm<<<128, 256, LSMEM>>>(W_hh);

    k_finalize<<<1, 256>>>(gamma, beta);

    // proj = affine(temp) @ W_lin^T + b_lin
    kg<1, 0, 0, 1><<<dim3(2, 2, 256), 256, GSMEM>>>(
        pTemp, nullptr, 65536, 256, W_lin, 0, 256,
        pProj, 65536, 256, b_lin, pQ, pR0, 256);

    // out = proj @ affine(temp)^T
    kg<0, 1, 0, 0><<<dim3(2, 2, 256), 256, GSMEM>>>(
        pProj, nullptr, 65536, 256, pTemp, 65536, 256,
        out, 65536, 256, nullptr, pQ, pR0, 256);
}

// round 4
// speedup vs baseline: 1.3661x; 1.0450x over previous
#include <cuda_runtime.h>
#include <cstdint>
#include <math.h>

#define Bd 8
#define Ld 32

// ---------------- device scratch ------------------------------------------
__device__ __align__(16) float g_w[256 * 256];
__device__ __align__(16) float g_Xr[(size_t)Bd * Ld * 256 * 256];     // rnd(X)
__device__ __align__(16) float g_Xw[(size_t)Bd * Ld * 256 * 256];     // rnd(X*w)
__device__ __align__(16) float g_Ecat[2 * 256 * 256];                 // rnd(E1;E2)
__device__ __align__(16) float g_Wih[1024 * 512];                     // rnd(W_ih)
__device__ __align__(16) float g_Wlin[256 * 256];                     // rnd(W_lin)
__device__ __align__(16) float g_Whr[1024 * 256];                     // rnd(W_hh)
__device__ __align__(16) float g_Fcat[1024 * 512];                    // rounded (RO)
__device__ __align__(16) float g_biasz[1024];
__device__ __align__(16) float g_xproj[(size_t)Bd * Ld * 256 * 1024];
__device__ __align__(16) float g_temp[(size_t)Bd * Ld * 256 * 256];   // rounded h
__device__ __align__(16) float g_proj[(size_t)Bd * Ld * 256 * 256];   // rounded (RO)
__device__ double g_sum[256], g_ssum[256];
__device__ float g_q[256], g_r0[256];
__device__ unsigned g_barcnt;
__device__ volatile unsigned g_bargen;

// ---------------- helpers --------------------------------------------------
__device__ __forceinline__ uint32_t f2tf(float f) {
    uint32_t u;
    asm("cvt.rna.tf32.f32 %0, %1;" : "=r"(u) : "f"(f));
    return u;
}
__device__ __forceinline__ float rnd32(float f) { return __uint_as_float(f2tf(f)); }

__device__ __forceinline__ void mma_tf32(float* d, const uint32_t* a, const uint32_t* b) {
    asm volatile(
        "mma.sync.aligned.m16n8k8.row.col.f32.tf32.tf32.f32 "
        "{%0,%1,%2,%3}, {%4,%5,%6,%7}, {%8,%9}, {%0,%1,%2,%3};\n"
        : "+f"(d[0]), "+f"(d[1]), "+f"(d[2]), "+f"(d[3])
        : "r"(a[0]), "r"(a[1]), "r"(a[2]), "r"(a[3]), "r"(b[0]), "r"(b[1]));
}
__device__ __forceinline__ float sigf(float x) { return 1.f / (1.f + expf(-x)); }

__device__ __forceinline__ void cp16(uint32_t s, const void* g) {
    asm volatile("cp.async.cg.shared.global [%0], [%1], 16;" :: "r"(s), "l"(g));
}
#define CPCOMMIT asm volatile("cp.async.commit_group;")
#define CPWAIT2 asm volatile("cp.async.wait_group 2;")
#define CPWAIT1 asm volatile("cp.async.wait_group 1;")
#define CPWAIT0 asm volatile("cp.async.wait_group 0;")

// ---------------- init ------------------------------------------------------
__global__ void k_init(const float* __restrict__ bih, const float* __restrict__ bhh) {
    int i = blockIdx.x * 256 + threadIdx.x;  // grid 4
    g_biasz[i] = bih[i] + bhh[i];
    if (i < 256) { g_sum[i] = 0.0; g_ssum[i] = 0.0; }
    if (i == 0) { g_barcnt = 0; g_bargen = 0; }
}

// ---------------- softmax of -dis, row-wise ---------------------------------
__global__ void k_softmax(const float* __restrict__ dis) {
    __shared__ float red[256];
    int o = blockIdx.x, t = threadIdx.x;
    float e = expf(-dis[o * 256 + t]);
    red[t] = e;
    __syncthreads();
    for (int s = 128; s > 0; s >>= 1) {
        if (t < s) red[t] += red[t + s];
        __syncthreads();
    }
    g_w[o * 256 + t] = e / red[0];
}

// ---------------- prep: tf32-rounded operand copies --------------------------
__global__ void k_prep(const float* __restrict__ X, const float* __restrict__ E1,
                       const float* __restrict__ E2, const float* __restrict__ W_ih,
                       const float* __restrict__ W_hh, const float* __restrict__ W_lin) {
    long i = (long)blockIdx.x * 256 + threadIdx.x;  // grid 65536
    int nd = (int)(i & 65535);
    float x = X[i];
    g_Xr[i] = rnd32(x);
    g_Xw[i] = rnd32(x * g_w[nd]);
    if (i < 131072) g_Ecat[i] = rnd32(i < 65536 ? E1[i] : E2[i - 65536]);
    if (i < 524288) g_Wih[i] = rnd32(W_ih[i]);
    if (i < 262144) g_Whr[i] = rnd32(W_hh[i]);
    if (i < 65536) g_Wlin[i] = rnd32(W_lin[i]);
}

// ---------------- 128x128 tf32 GEMM, 3-stage cp.async -----------------------
// C = A' @ Bt^T (+bias). AMODE=1: A <- cvt(q[k]*A + r0[k]); else A pre-rounded.
// BMODE likewise for Bt. AHALF: k>=256 reads A2. HB: +bias[col]. RO: round C.
template <int AMODE, int BMODE, int AHALF, int HB, int RO>
__global__ void __launch_bounds__(256, 2) kg(
    const float* __restrict__ A, const float* __restrict__ A2, long sA, int lda,
    const float* __restrict__ Bt, long sB, int ldb,
    float* __restrict__ C, long sC, int ldc,
    const float* __restrict__ bias,
    const float* __restrict__ qv, const float* __restrict__ rv, int K) {
    extern __shared__ float sm[];
    __shared__ float qs[256], rs[256];

    const int tid = threadIdx.x;
    const int z = blockIdx.z;
    const float* Ab = A + sA * z;
    const float* Ab2 = AHALF ? (A2 + sA * z) : nullptr;
    const float* Bb = Bt + sB * z;
    float* Cb = C + sC * z;
    const int row0 = blockIdx.x * 128, col0 = blockIdx.y * 128;

    if (AMODE == 1 || BMODE == 1) {
        qs[tid & 255] = qv[tid & 255];
        rs[tid & 255] = rv[tid & 255];
        __syncthreads();
    }

    const int lane = tid & 31, wid = tid >> 5;
    const int wm = (wid >> 2) * 64, wn = (wid & 3) * 32;
    const int g = lane >> 2, tq = lane & 3;
    const int rA = tid >> 3, c4 = (tid & 7) * 4;
    const int nk = K / 32;
    const int STG = 2 * 128 * 36;  // floats per stage (A then B)

    auto load = [&](int s, int k0) {
        const float* Asrc;
        int kc;
        if (AHALF && k0 >= 256) { Asrc = Ab2; kc = k0 - 256 + c4; }
        else { Asrc = Ab; kc = k0 + c4; }
        uint32_t ab = (uint32_t)__cvta_generic_to_shared(sm + s * STG);
        uint32_t bb = ab + 128 * 36 * 4;
#pragma unroll
        for (int i = 0; i < 4; i++) {
            int r = rA + i * 32;
            cp16(ab + (r * 36 + c4) * 4, Asrc + (long)(row0 + r) * lda + kc);
        }
#pragma unroll
        for (int i = 0; i < 4; i++) {
            int r = rA + i * 32;
            cp16(bb + (r * 36 + c4) * 4, Bb + (long)(col0 + r) * ldb + k0 + c4);
        }
        CPCOMMIT;
    };

    float acc[4][4][4] = {};
    load(0, 0);
    load(1, 32);
    for (int kt = 0; kt < nk; kt++) {
        if (kt + 2 < nk) { load((kt + 2) % 3, (kt + 2) * 32); CPWAIT2; }
        else if (kt + 1 < nk) { CPWAIT1; }
        else { CPWAIT0; }
        __syncthreads();
        const float* as = sm + (kt % 3) * STG;
        const float* bs = as + 128 * 36;
        const uint32_t* asu = (const uint32_t*)as;
        const uint32_t* bsu = (const uint32_t*)bs;
        const int k0 = kt * 32;
#pragma unroll
        for (int kk = 0; kk < 32; kk += 8) {
            uint32_t af[4][4], bf[4][2];
            const int kA = k0 + kk + tq;
#pragma unroll
            for (int mi = 0; mi < 4; mi++) {
                int base = (wm + mi * 16 + g) * 36 + kk + tq;
                if (AMODE == 1) {
                    float a0 = as[base], a1 = as[base + 36 * 8];
                    float a2 = as[base + 4], a3 = as[base + 36 * 8 + 4];
                    af[mi][0] = f2tf(a0 * qs[kA] + rs[kA]);
                    af[mi][1] = f2tf(a1 * qs[kA] + rs[kA]);
                    af[mi][2] = f2tf(a2 * qs[kA + 4] + rs[kA + 4]);
                    af[mi][3] = f2tf(a3 * qs[kA + 4] + rs[kA + 4]);
                } else {
                    af[mi][0] = asu[base];       af[mi][1] = asu[base + 36 * 8];
                    af[mi][2] = asu[base + 4];   af[mi][3] = asu[base + 36 * 8 + 4];
                }
            }
#pragma unroll
            for (int ni = 0; ni < 4; ni++) {
                int base = (wn + ni * 8 + g) * 36 + kk + tq;
                if (BMODE == 1) {
                    bf[ni][0] = f2tf(bs[base] * qs[kA] + rs[kA]);
                    bf[ni][1] = f2tf(bs[base + 4] * qs[kA + 4] + rs[kA + 4]);
                } else {
                    bf[ni][0] = bsu[base];
                    bf[ni][1] = bsu[base + 4];
                }
            }
#pragma unroll
            for (int mi = 0; mi < 4; mi++)
#pragma unroll
                for (int ni = 0; ni < 4; ni++) mma_tf32(acc[mi][ni], af[mi], bf[ni]);
        }
        __syncthreads();
    }
#pragma unroll
    for (int mi = 0; mi < 4; mi++) {
        int rr = row0 + wm + mi * 16 + g;
#pragma unroll
        for (int ni = 0; ni < 4; ni++) {
            int cc = col0 + wn + ni * 8 + tq * 2;
            float b0 = HB ? bias[cc] : 0.f, b1 = HB ? bias[cc + 1] : 0.f;
            float v0 = acc[mi][ni][0] + b0, v1 = acc[mi][ni][1] + b1;
            float v2 = acc[mi][ni][2] + b0, v3 = acc[mi][ni][3] + b1;
            if (RO) { v0 = rnd32(v0); v1 = rnd32(v1); v2 = rnd32(v2); v3 = rnd32(v3); }
            Cb[(long)rr * ldc + cc] = v0;
            Cb[(long)rr * ldc + cc + 1] = v1;
            Cb[(long)(rr + 8) * ldc + cc] = v2;
            Cb[(long)(rr + 8) * ldc + cc + 1] = v3;
        }
    }
}

// ---------------- grid barrier ----------------------------------------------
__device__ __forceinline__ void gridbar(unsigned nb, unsigned& mygen) {
    __syncthreads();
    if (threadIdx.x == 0) {
        __threadfence();
        unsigned old = atomicAdd(&g_barcnt, 1u);
        if (old == nb - 1) {
            g_barcnt = 0;
            __threadfence();
            atomicAdd((unsigned*)&g_bargen, 1u);
        } else {
            while (g_bargen <= mygen) {}
        }
        __threadfence();
    }
    __syncthreads();
    mygen++;
}

// ---------------- persistent fused LSTM (pre-rounded operands) ---------------
__global__ void __launch_bounds__(256, 1) k_lstm() {
    extern __shared__ float sm[];
    float* As = sm;                       // 2*64*36
    float* Bs = sm + 2 * 64 * 36;         // 2*256*36
    float* Zs = Bs + 2 * 256 * 36;        // 64*260
    float* Xp = Zs + 64 * 260;            // 64*256

    const int tid = threadIdx.x;
    const int bid = blockIdx.x;
    const int rows0 = (bid >> 2) * 64, m0 = (bid & 3) * 64;
    const int b = rows0 >> 8, n0 = rows0 & 255;
    const int lane = tid & 31, wid = tid >> 5;
    const int wm = (wid >> 2) * 32, wn = (wid & 3) * 64;
    const int g = lane >> 2, tq = lane & 3;
    const int rA = tid >> 3, c4 = (tid & 7) * 4;
    const int ml = tid & 63, rg = tid >> 6;

    float creg[16];
#pragma unroll
    for (int i = 0; i < 16; i++) creg[i] = 0.f;
    double sd = 0.0, ssd = 0.0;
    unsigned mygen = 0;

    const uint32_t xb = (uint32_t)__cvta_generic_to_shared(Xp);

    for (int t = 0; t < Ld; t++) {
        const long xz = ((long)b * Ld + t) * 256;
        {
#pragma unroll
            for (int k = 0; k < 16; k++) {
                int c = tid + k * 256;
                int row = c >> 6;
                int col4 = (c & 63) * 4;
                int gate = col4 >> 6, mcol = col4 & 63;
                cp16(xb + (row * 256 + col4) * 4,
                     g_xproj + (xz + n0 + row) * 1024 + gate * 256 + m0 + mcol);
            }
            CPCOMMIT;
        }

        float acc[2][8][4] = {};
        if (t > 0) {
            const float* Ab = g_temp + (((long)b * Ld + (t - 1)) * 256 + n0) * 256;
            auto load = [&](int stg, int k0) {
                uint32_t ab = (uint32_t)__cvta_generic_to_shared(As + stg * 64 * 36);
                uint32_t bb = (uint32_t)__cvta_generic_to_shared(Bs + stg * 256 * 36);
#pragma unroll
                for (int i = 0; i < 2; i++) {
                    int r = rA + i * 32;
                    cp16(ab + (r * 36 + c4) * 4, Ab + (long)r * 256 + k0 + c4);
                }
#pragma unroll
                for (int i = 0; i < 8; i++) {
                    int ng = rA + i * 32;
                    int wrow = (ng >> 6) * 256 + m0 + (ng & 63);
                    cp16(bb + (ng * 36 + c4) * 4, g_Whr + (long)wrow * 256 + k0 + c4);
                }
                CPCOMMIT;
            };
            load(0, 0);
            for (int kt = 0; kt < 8; kt++) {
                if (kt < 7) { load((kt + 1) & 1, (kt + 1) * 32); CPWAIT1; }
                else { CPWAIT0; }
                __syncthreads();
                const uint32_t* as = (const uint32_t*)(As + (kt & 1) * 64 * 36);
                const uint32_t* bs = (const uint32_t*)(Bs + (kt & 1) * 256 * 36);
#pragma unroll
                for (int kk = 0; kk < 32; kk += 8) {
                    uint32_t af[2][4], bf[8][2];
#pragma unroll
                    for (int mi = 0; mi < 2; mi++) {
                        int base = (wm + mi * 16 + g) * 36 + kk + tq;
                        af[mi][0] = as[base];     af[mi][1] = as[base + 36 * 8];
                        af[mi][2] = as[base + 4]; af[mi][3] = as[base + 36 * 8 + 4];
                    }
#pragma unroll
                    for (int ni = 0; ni < 8; ni++) {
                        int base = (wn + ni * 8 + g) * 36 + kk + tq;
                        bf[ni][0] = bs[base]; bf[ni][1] = bs[base + 4];
                    }
#pragma unroll
                    for (int mi = 0; mi < 2; mi++)
#pragma unroll
                        for (int ni = 0; ni < 8; ni++) mma_tf32(acc[mi][ni], af[mi], bf[ni]);
                }
                __syncthreads();
            }
        } else {
            CPWAIT0;
            __syncthreads();
        }

#pragma unroll
        for (int mi = 0; mi < 2; mi++) {
            int zr = wm + mi * 16 + g;
#pragma unroll
            for (int ni = 0; ni < 8; ni++) {
                int zc = wn + ni * 8 + tq * 2;
                Zs[zr * 260 + zc] = acc[mi][ni][0];
                Zs[zr * 260 + zc + 1] = acc[mi][ni][1];
                Zs[(zr + 8) * 260 + zc] = acc[mi][ni][2];
                Zs[(zr + 8) * 260 + zc + 1] = acc[mi][ni][3];
            }
        }
        __syncthreads();

        float ps = 0.f, pss = 0.f;
#pragma unroll 4
        for (int i = 0; i < 16; i++) {
            int r = rg * 16 + i;
            int nn = n0 + r;
            float zi = Zs[r * 260 + ml] + Xp[r * 256 + ml];
            float zf = Zs[r * 260 + 64 + ml] + Xp[r * 256 + 64 + ml];
            float zg = Zs[r * 260 + 128 + ml] + Xp[r * 256 + 128 + ml];
            float zo = Zs[r * 260 + 192 + ml] + Xp[r * 256 + 192 + ml];
            float ig = sigf(zi), fg = sigf(zf), gg = tanhf(zg), og = sigf(zo);
            float c = fg * creg[i] + ig * gg;
            creg[i] = c;
            float h = rnd32(og * tanhf(c));   // rounded: GEMM-ready
            g_temp[(xz + nn) * 256 + m0 + ml] = h;
            ps += h; pss += h * h;
        }
        sd += (double)ps; ssd += (double)pss;

        if (t < Ld - 1) gridbar(128, mygen);
    }
    atomicAdd(&g_sum[m0 + ml], sd);
    atomicAdd(&g_ssum[m0 + ml], ssd);
}

// ---------------- BN finalize -------------------------------------------------
__global__ void k_finalize(const float* __restrict__ gamma, const float* __restrict__ beta) {
    int m = threadIdx.x;
    double mu = g_sum[m] / 65536.0;
    double var = g_ssum[m] / 65536.0 - mu * mu;
    float q = gamma[m] * (float)(1.0 / sqrt(var + 1e-5));
    g_q[m] = q;
    g_r0[m] = beta[m] - (float)mu * q;
}

// ---------------- launch ------------------------------------------------------
extern "C" void kernel_launch(void* const* d_in, const int* in_sizes, int n_in,
                              void* d_out, int out_size) {
    const float* X     = (const float*)d_in[0];
    const float* dis   = (const float*)d_in[1];
    const float* E1    = (const float*)d_in[2];
    const float* E2    = (const float*)d_in[3];
    const float* W_ih  = (const float*)d_in[4];
    const float* W_hh  = (const float*)d_in[5];
    const float* b_ih  = (const float*)d_in[6];
    const float* b_hh  = (const float*)d_in[7];
    const float* gamma = (const float*)d_in[8];
    const float* beta  = (const float*)d_in[9];
    const float* W_lin = (const float*)d_in[10];
    const float* b_lin = (const float*)d_in[11];
    float* out = (float*)d_out;

    const int GSMEM = 3 * 2 * 128 * 36 * 4;   // 110592 B (3-stage)
    const int LSMEM = (2 * 64 * 36 + 2 * 256 * 36 + 64 * 260 + 64 * 256) * 4;

    cudaFuncSetAttribute(kg<0, 0, 0, 0, 1>, cudaFuncAttributeMaxDynamicSharedMemorySize, GSMEM);
    cudaFuncSetAttribute(kg<0, 0, 1, 1, 0>, cudaFuncAttributeMaxDynamicSharedMemorySize, GSMEM);
    cudaFuncSetAttribute(kg<1, 0, 0, 1, 1>, cudaFuncAttributeMaxDynamicSharedMemorySize, GSMEM);
    cudaFuncSetAttribute(kg<0, 1, 0, 0, 0>, cudaFuncAttributeMaxDynamicSharedMemorySize, GSMEM);
    cudaFuncSetAttribute(k_lstm, cudaFuncAttributeMaxDynamicSharedMemorySize, LSMEM);

    float *pXr, *pXw, *pEcat, *pWih, *pWlin, *pFcat, *pBiasz, *pXproj, *pTemp, *pProj, *pQ, *pR0;
    cudaGetSymbolAddress((void**)&pXr, g_Xr);
    cudaGetSymbolAddress((void**)&pXw, g_Xw);
    cudaGetSymbolAddress((void**)&pEcat, g_Ecat);
    cudaGetSymbolAddress((void**)&pWih, g_Wih);
    cudaGetSymbolAddress((void**)&pWlin, g_Wlin);
    cudaGetSymbolAddress((void**)&pFcat, g_Fcat);
    cudaGetSymbolAddress((void**)&pBiasz, g_biasz);
    cudaGetSymbolAddress((void**)&pXproj, g_xproj);
    cudaGetSymbolAddress((void**)&pTemp, g_temp);
    cudaGetSymbolAddress((void**)&pProj, g_proj);
    cudaGetSymbolAddress((void**)&pQ, g_q);
    cudaGetSymbolAddress((void**)&pR0, g_r0);

    k_init<<<4, 256>>>(b_ih, b_hh);
    k_softmax<<<256, 256>>>(dis);
    k_prep<<<65536, 256>>>(X, E1, E2, W_ih, W_hh, W_lin);

    // Fcat[j,0:256]=Wih[:,0:256]@E1^T ; Fcat[j,256:512]=Wih[:,256:512]@E2^T  (rounded)
    kg<0, 0, 0, 0, 1><<<dim3(8, 2, 2), 256, GSMEM>>>(
        pWih, nullptr, 256, 512, pEcat, 65536, 256,
        pFcat, 256, 512, nullptr, nullptr, nullptr, 256);

    // xproj = [Xr | Xw] @ Fcat^T + biasz  (K=512), per (b,l)
    kg<0, 0, 1, 1, 0><<<dim3(2, 8, 256), 256, GSMEM>>>(
        pXr, pXw, 65536, 256, pFcat, 0, 512,
        pXproj, 262144, 1024, pBiasz, nullptr, nullptr, 512);

    // persistent LSTM (+BN stats)
    k_lstm<<<128, 256, LSMEM>>>();

    k_finalize<<<1, 256>>>(gamma, beta);

    // proj = cvt(affine(temp)) @ Wlin^T + b_lin   (output rounded)
    kg<1, 0, 0, 1, 1><<<dim3(2, 2, 256), 256, GSMEM>>>(
        pTemp, nullptr, 65536, 256, pWlin, 0, 256,
        pProj, 65536, 256, b_lin, pQ, pR0, 256);

    // out = proj @ cvt(affine(temp))^T
    kg<0, 1, 0, 0, 0><<<dim3(2, 2, 256), 256, GSMEM>>>(
        pProj, nullptr, 65536, 256, pTemp, 65536, 256,
        out, 65536, 256, nullptr, pQ, pR0, 256);
}

// round 5
// speedup vs baseline: 1.4276x; 1.0450x over previous
#include <cuda_runtime.h>
#include <cstdint>
#include <math.h>

#define Bd 8
#define Ld 32

// ---------------- device scratch ------------------------------------------
__device__ __align__(16) float g_w[256 * 256];
__device__ __align__(16) float g_Xr[(size_t)Bd * Ld * 256 * 256];     // rnd(X)
__device__ __align__(16) float g_Xw[(size_t)Bd * Ld * 256 * 256];     // rnd(X*w)
__device__ __align__(16) float g_Ecat[2 * 256 * 256];                 // rnd(E1;E2)
__device__ __align__(16) float g_Wih[1024 * 512];                     // rnd(W_ih)
__device__ __align__(16) float g_Wlin[256 * 256];                     // rnd(W_lin)
__device__ __align__(16) float g_Whr[1024 * 256];                     // rnd(W_hh)
__device__ __align__(16) float g_Fcat[1024 * 512];                    // rounded (RO)
__device__ __align__(16) float g_biasz[1024];
__device__ __align__(16) float g_xproj[(size_t)Bd * Ld * 256 * 1024];
__device__ __align__(16) float g_temp[(size_t)Bd * Ld * 256 * 256];   // rounded h
__device__ __align__(16) float g_proj[(size_t)Bd * Ld * 256 * 256];   // rounded (RO)
__device__ double g_sum[256], g_ssum[256];
__device__ float g_q[256], g_r0[256];
__device__ unsigned g_barcnt;
__device__ volatile unsigned g_bargen;

// ---------------- helpers --------------------------------------------------
__device__ __forceinline__ uint32_t f2tf(float f) {
    uint32_t u;
    asm("cvt.rna.tf32.f32 %0, %1;" : "=r"(u) : "f"(f));
    return u;
}
__device__ __forceinline__ float rnd32(float f) { return __uint_as_float(f2tf(f)); }

__device__ __forceinline__ void mma_tf32(float* d, const uint32_t* a, const uint32_t* b) {
    asm volatile(
        "mma.sync.aligned.m16n8k8.row.col.f32.tf32.tf32.f32 "
        "{%0,%1,%2,%3}, {%4,%5,%6,%7}, {%8,%9}, {%0,%1,%2,%3};\n"
        : "+f"(d[0]), "+f"(d[1]), "+f"(d[2]), "+f"(d[3])
        : "r"(a[0]), "r"(a[1]), "r"(a[2]), "r"(a[3]), "r"(b[0]), "r"(b[1]));
}
__device__ __forceinline__ float sigf(float x) { return 1.f / (1.f + expf(-x)); }

__device__ __forceinline__ void cp16(uint32_t s, const void* g) {
    asm volatile("cp.async.cg.shared.global [%0], [%1], 16;" :: "r"(s), "l"(g));
}
#define CPCOMMIT asm volatile("cp.async.commit_group;")
#define CPWAIT1 asm volatile("cp.async.wait_group 1;")
#define CPWAIT0 asm volatile("cp.async.wait_group 0;")

// ---------------- init ------------------------------------------------------
__global__ void k_init(const float* __restrict__ bih, const float* __restrict__ bhh) {
    int i = blockIdx.x * 256 + threadIdx.x;  // grid 4
    g_biasz[i] = bih[i] + bhh[i];
    if (i < 256) { g_sum[i] = 0.0; g_ssum[i] = 0.0; }
    if (i == 0) { g_barcnt = 0; g_bargen = 0; }
}

// ---------------- softmax of -dis, row-wise ---------------------------------
__global__ void k_softmax(const float* __restrict__ dis) {
    __shared__ float red[256];
    int o = blockIdx.x, t = threadIdx.x;
    float e = expf(-dis[o * 256 + t]);
    red[t] = e;
    __syncthreads();
    for (int s = 128; s > 0; s >>= 1) {
        if (t < s) red[t] += red[t + s];
        __syncthreads();
    }
    g_w[o * 256 + t] = e / red[0];
}

// ---------------- prep: tf32-rounded operand copies (float4) -----------------
__global__ void k_prep(const float4* __restrict__ X, const float4* __restrict__ E1,
                       const float4* __restrict__ E2, const float4* __restrict__ W_ih,
                       const float4* __restrict__ W_hh, const float4* __restrict__ W_lin) {
    long i = (long)blockIdx.x * 256 + threadIdx.x;  // grid 16384 -> 4.19M float4
    int nd = (int)(i & 16383);
    float4 x = X[i];
    float4 w = ((const float4*)g_w)[nd];
    float4 o1, o2;
    o1.x = rnd32(x.x); o1.y = rnd32(x.y); o1.z = rnd32(x.z); o1.w = rnd32(x.w);
    o2.x = rnd32(x.x * w.x); o2.y = rnd32(x.y * w.y);
    o2.z = rnd32(x.z * w.z); o2.w = rnd32(x.w * w.w);
    ((float4*)g_Xr)[i] = o1;
    ((float4*)g_Xw)[i] = o2;
    if (i < 32768) {
        float4 e = (i < 16384) ? E1[i] : E2[i - 16384];
        e.x = rnd32(e.x); e.y = rnd32(e.y); e.z = rnd32(e.z); e.w = rnd32(e.w);
        ((float4*)g_Ecat)[i] = e;
    }
    if (i < 131072) {
        float4 v = W_ih[i];
        v.x = rnd32(v.x); v.y = rnd32(v.y); v.z = rnd32(v.z); v.w = rnd32(v.w);
        ((float4*)g_Wih)[i] = v;
    }
    if (i < 65536) {
        float4 v = W_hh[i];
        v.x = rnd32(v.x); v.y = rnd32(v.y); v.z = rnd32(v.z); v.w = rnd32(v.w);
        ((float4*)g_Whr)[i] = v;
    }
    if (i < 16384) {
        float4 v = W_lin[i];
        v.x = rnd32(v.x); v.y = rnd32(v.y); v.z = rnd32(v.z); v.w = rnd32(v.w);
        ((float4*)g_Wlin)[i] = v;
    }
}

// ---------------- 128x128 tf32 GEMM, 128 threads, 64x64 warp tile -----------
// C = A' @ Bt^T (+bias). AMODE=1: A frag <- cvt(q[k]*A + r0[k]) (A raw fp32).
// BMODE likewise. AHALF: k>=256 reads A2. HB: +bias[col]. RO: round C to tf32.
template <int AMODE, int BMODE, int AHALF, int HB, int RO>
__global__ void __launch_bounds__(128, 2) kg(
    const float* __restrict__ A, const float* __restrict__ A2, long sA, int lda,
    const float* __restrict__ Bt, long sB, int ldb,
    float* __restrict__ C, long sC, int ldc,
    const float* __restrict__ bias,
    const float* __restrict__ qv, const float* __restrict__ rv, int K) {
    extern __shared__ float sm[];     // 2 stages x (A 128x36 + B 128x36)
    __shared__ float qs[256], rs[256];

    const int tid = threadIdx.x;
    const int z = blockIdx.z;
    const float* Ab = A + sA * z;
    const float* Ab2 = AHALF ? (A2 + sA * z) : nullptr;
    const float* Bb = Bt + sB * z;
    float* Cb = C + sC * z;
    const int row0 = blockIdx.x * 128, col0 = blockIdx.y * 128;

    if (AMODE == 1 || BMODE == 1) {
        qs[tid] = qv[tid]; qs[tid + 128] = qv[tid + 128];
        rs[tid] = rv[tid]; rs[tid + 128] = rv[tid + 128];
        __syncthreads();
    }

    const int lane = tid & 31, wid = tid >> 5;      // 4 warps
    const int wm = (wid >> 1) * 64, wn = (wid & 1) * 64;
    const int g = lane >> 2, tq = lane & 3;
    const int rL = tid >> 3, c4 = (tid & 7) * 4;
    const int nk = K / 32;
    const int STG = 2 * 128 * 36;   // floats per stage

    auto load = [&](int s, int k0) {
        const float* Asrc;
        int kc;
        if (AHALF && k0 >= 256) { Asrc = Ab2; kc = k0 - 256 + c4; }
        else { Asrc = Ab; kc = k0 + c4; }
        uint32_t ab = (uint32_t)__cvta_generic_to_shared(sm + s * STG);
        uint32_t bb = ab + 128 * 36 * 4;
#pragma unroll
        for (int i = 0; i < 8; i++) {
            int r = rL + i * 16;
            cp16(ab + (r * 36 + c4) * 4, Asrc + (long)(row0 + r) * lda + kc);
        }
#pragma unroll
        for (int i = 0; i < 8; i++) {
            int r = rL + i * 16;
            cp16(bb + (r * 36 + c4) * 4, Bb + (long)(col0 + r) * ldb + k0 + c4);
        }
        CPCOMMIT;
    };

    float acc[4][8][4] = {};
    load(0, 0);
    load(1, 32);
    for (int kt = 0; kt < nk; kt++) {
        if (kt + 1 < nk) { CPWAIT1; } else { CPWAIT0; }
        __syncthreads();
        const float* as = sm + (kt & 1) * STG;
        const float* bs = as + 128 * 36;
        const uint32_t* asu = (const uint32_t*)as;
        const uint32_t* bsu = (const uint32_t*)bs;
        const int k0 = kt * 32;
#pragma unroll
        for (int kk = 0; kk < 32; kk += 8) {
            uint32_t af[4][4], bf[8][2];
            const int kA = k0 + kk + tq;
#pragma unroll
            for (int mi = 0; mi < 4; mi++) {
                int base = (wm + mi * 16 + g) * 36 + kk + tq;
                if (AMODE == 1) {
                    af[mi][0] = f2tf(as[base] * qs[kA] + rs[kA]);
                    af[mi][1] = f2tf(as[base + 36 * 8] * qs[kA] + rs[kA]);
                    af[mi][2] = f2tf(as[base + 4] * qs[kA + 4] + rs[kA + 4]);
                    af[mi][3] = f2tf(as[base + 36 * 8 + 4] * qs[kA + 4] + rs[kA + 4]);
                } else {
                    af[mi][0] = asu[base];       af[mi][1] = asu[base + 36 * 8];
                    af[mi][2] = asu[base + 4];   af[mi][3] = asu[base + 36 * 8 + 4];
                }
            }
#pragma unroll
            for (int ni = 0; ni < 8; ni++) {
                int base = (wn + ni * 8 + g) * 36 + kk + tq;
                if (BMODE == 1) {
                    bf[ni][0] = f2tf(bs[base] * qs[kA] + rs[kA]);
                    bf[ni][1] = f2tf(bs[base + 4] * qs[kA + 4] + rs[kA + 4]);
                } else {
                    bf[ni][0] = bsu[base];
                    bf[ni][1] = bsu[base + 4];
                }
            }
#pragma unroll
            for (int mi = 0; mi < 4; mi++)
#pragma unroll
                for (int ni = 0; ni < 8; ni++) mma_tf32(acc[mi][ni], af[mi], bf[ni]);
        }
        __syncthreads();
        if (kt + 2 < nk) load(kt & 1, (kt + 2) * 32);
    }
#pragma unroll
    for (int mi = 0; mi < 4; mi++) {
        int rr = row0 + wm + mi * 16 + g;
#pragma unroll
        for (int ni = 0; ni < 8; ni++) {
            int cc = col0 + wn + ni * 8 + tq * 2;
            float b0 = HB ? bias[cc] : 0.f, b1 = HB ? bias[cc + 1] : 0.f;
            float v0 = acc[mi][ni][0] + b0, v1 = acc[mi][ni][1] + b1;
            float v2 = acc[mi][ni][2] + b0, v3 = acc[mi][ni][3] + b1;
            if (RO) { v0 = rnd32(v0); v1 = rnd32(v1); v2 = rnd32(v2); v3 = rnd32(v3); }
            Cb[(long)rr * ldc + cc] = v0;
            Cb[(long)rr * ldc + cc + 1] = v1;
            Cb[(long)(rr + 8) * ldc + cc] = v2;
            Cb[(long)(rr + 8) * ldc + cc + 1] = v3;
        }
    }
}

// ---------------- grid barrier ----------------------------------------------
__device__ __forceinline__ void gridbar(unsigned nb, unsigned& mygen) {
    __syncthreads();
    if (threadIdx.x == 0) {
        __threadfence();
        unsigned old = atomicAdd(&g_barcnt, 1u);
        if (old == nb - 1) {
            g_barcnt = 0;
            __threadfence();
            atomicAdd((unsigned*)&g_bargen, 1u);
        } else {
            while (g_bargen <= mygen) {}
        }
        __threadfence();
    }
    __syncthreads();
    mygen++;
}

// ---------------- persistent fused LSTM (pre-rounded operands) ---------------
__global__ void __launch_bounds__(256, 1) k_lstm() {
    extern __shared__ float sm[];
    float* As = sm;                       // 2*64*36
    float* Bs = sm + 2 * 64 * 36;         // 2*256*36
    float* Zs = Bs + 2 * 256 * 36;        // 64*260
    float* Xp = Zs + 64 * 260;            // 64*256

    const int tid = threadIdx.x;
    const int bid = blockIdx.x;
    const int rows0 = (bid >> 2) * 64, m0 = (bid & 3) * 64;
    const int b = rows0 >> 8, n0 = rows0 & 255;
    const int lane = tid & 31, wid = tid >> 5;
    const int wm = (wid >> 2) * 32, wn = (wid & 3) * 64;
    const int g = lane >> 2, tq = lane & 3;
    const int rA = tid >> 3, c4 = (tid & 7) * 4;
    const int ml = tid & 63, rg = tid >> 6;

    float creg[16];
#pragma unroll
    for (int i = 0; i < 16; i++) creg[i] = 0.f;
    double sd = 0.0, ssd = 0.0;
    unsigned mygen = 0;

    const uint32_t xb = (uint32_t)__cvta_generic_to_shared(Xp);

    for (int t = 0; t < Ld; t++) {
        const long xz = ((long)b * Ld + t) * 256;
        {
#pragma unroll
            for (int k = 0; k < 16; k++) {
                int c = tid + k * 256;
                int row = c >> 6;
                int col4 = (c & 63) * 4;
                int gate = col4 >> 6, mcol = col4 & 63;
                cp16(xb + (row * 256 + col4) * 4,
                     g_xproj + (xz + n0 + row) * 1024 + gate * 256 + m0 + mcol);
            }
            CPCOMMIT;
        }

        float acc[2][8][4] = {};
        if (t > 0) {
            const float* Ab = g_temp + (((long)b * Ld + (t - 1)) * 256 + n0) * 256;
            auto load = [&](int stg, int k0) {
                uint32_t ab = (uint32_t)__cvta_generic_to_shared(As + stg * 64 * 36);
                uint32_t bb = (uint32_t)__cvta_generic_to_shared(Bs + stg * 256 * 36);
#pragma unroll
                for (int i = 0; i < 2; i++) {
                    int r = rA + i * 32;
                    cp16(ab + (r * 36 + c4) * 4, Ab + (long)r * 256 + k0 + c4);
                }
#pragma unroll
                for (int i = 0; i < 8; i++) {
                    int ng = rA + i * 32;
                    int wrow = (ng >> 6) * 256 + m0 + (ng & 63);
                    cp16(bb + (ng * 36 + c4) * 4, g_Whr + (long)wrow * 256 + k0 + c4);
                }
                CPCOMMIT;
            };
            load(0, 0);
            for (int kt = 0; kt < 8; kt++) {
                if (kt < 7) { load((kt + 1) & 1, (kt + 1) * 32); CPWAIT1; }
                else { CPWAIT0; }
                __syncthreads();
                const uint32_t* as = (const uint32_t*)(As + (kt & 1) * 64 * 36);
                const uint32_t* bs = (const uint32_t*)(Bs + (kt & 1) * 256 * 36);
#pragma unroll
                for (int kk = 0; kk < 32; kk += 8) {
                    uint32_t af[2][4], bf[8][2];
#pragma unroll
                    for (int mi = 0; mi < 2; mi++) {
                        int base = (wm + mi * 16 + g) * 36 + kk + tq;
                        af[mi][0] = as[base];     af[mi][1] = as[base + 36 * 8];
                        af[mi][2] = as[base + 4]; af[mi][3] = as[base + 36 * 8 + 4];
                    }
#pragma unroll
                    for (int ni = 0; ni < 8; ni++) {
                        int base = (wn + ni * 8 + g) * 36 + kk + tq;
                        bf[ni][0] = bs[base]; bf[ni][1] = bs[base + 4];
                    }
#pragma unroll
                    for (int mi = 0; mi < 2; mi++)
#pragma unroll
                        for (int ni = 0; ni < 8; ni++) mma_tf32(acc[mi][ni], af[mi], bf[ni]);
                }
                __syncthreads();
            }
        } else {
            CPWAIT0;
            __syncthreads();
        }

#pragma unroll
        for (int mi = 0; mi < 2; mi++) {
            int zr = wm + mi * 16 + g;
#pragma unroll
            for (int ni = 0; ni < 8; ni++) {
                int zc = wn + ni * 8 + tq * 2;
                Zs[zr * 260 + zc] = acc[mi][ni][0];
                Zs[zr * 260 + zc + 1] = acc[mi][ni][1];
                Zs[(zr + 8) * 260 + zc] = acc[mi][ni][2];
                Zs[(zr + 8) * 260 + zc + 1] = acc[mi][ni][3];
            }
        }
        __syncthreads();

        float ps = 0.f, pss = 0.f;
#pragma unroll 4
        for (int i = 0; i < 16; i++) {
            int r = rg * 16 + i;
            int nn = n0 + r;
            float zi = Zs[r * 260 + ml] + Xp[r * 256 + ml];
            float zf = Zs[r * 260 + 64 + ml] + Xp[r * 256 + 64 + ml];
            float zg = Zs[r * 260 + 128 + ml] + Xp[r * 256 + 128 + ml];
            float zo = Zs[r * 260 + 192 + ml] + Xp[r * 256 + 192 + ml];
            float ig = sigf(zi), fg = sigf(zf), gg = tanhf(zg), og = sigf(zo);
            float c = fg * creg[i] + ig * gg;
            creg[i] = c;
            float h = rnd32(og * tanhf(c));
            g_temp[(xz + nn) * 256 + m0 + ml] = h;
            ps += h; pss += h * h;
        }
        sd += (double)ps; ssd += (double)pss;

        if (t < Ld - 1) gridbar(128, mygen);
    }
    atomicAdd(&g_sum[m0 + ml], sd);
    atomicAdd(&g_ssum[m0 + ml], ssd);
}

// ---------------- BN finalize -------------------------------------------------
__global__ void k_finalize(const float* __restrict__ gamma, const float* __restrict__ beta) {
    int m = threadIdx.x;
    double mu = g_sum[m] / 65536.0;
    double var = g_ssum[m] / 65536.0 - mu * mu;
    float q = gamma[m] * (float)(1.0 / sqrt(var + 1e-5));
    g_q[m] = q;
    g_r0[m] = beta[m] - (float)mu * q;
}

// ---------------- launch ------------------------------------------------------
extern "C" void kernel_launch(void* const* d_in, const int* in_sizes, int n_in,
                              void* d_out, int out_size) {
    const float* X     = (const float*)d_in[0];
    const float* dis   = (const float*)d_in[1];
    const float* E1    = (const float*)d_in[2];
    const float* E2    = (const float*)d_in[3];
    const float* W_ih  = (const float*)d_in[4];
    const float* W_hh  = (const float*)d_in[5];
    const float* b_ih  = (const float*)d_in[6];
    const float* b_hh  = (const float*)d_in[7];
    const float* gamma = (const float*)d_in[8];
    const float* beta  = (const float*)d_in[9];
    const float* W_lin = (const float*)d_in[10];
    const float* b_lin = (const float*)d_in[11];
    float* out = (float*)d_out;

    const int GSMEM = 2 * 2 * 128 * 36 * 4;   // 73728 B (2-stage, 128-thr kernel)
    const int LSMEM = (2 * 64 * 36 + 2 * 256 * 36 + 64 * 260 + 64 * 256) * 4;

    cudaFuncSetAttribute(kg<0, 0, 0, 0, 1>, cudaFuncAttributeMaxDynamicSharedMemorySize, GSMEM);
    cudaFuncSetAttribute(kg<0, 0, 1, 1, 0>, cudaFuncAttributeMaxDynamicSharedMemorySize, GSMEM);
    cudaFuncSetAttribute(kg<1, 0, 0, 1, 1>, cudaFuncAttributeMaxDynamicSharedMemorySize, GSMEM);
    cudaFuncSetAttribute(kg<0, 1, 0, 0, 0>, cudaFuncAttributeMaxDynamicSharedMemorySize, GSMEM);
    cudaFuncSetAttribute(k_lstm, cudaFuncAttributeMaxDynamicSharedMemorySize, LSMEM);

    float *pXr, *pXw, *pEcat, *pWih, *pWlin, *pFcat, *pBiasz, *pXproj, *pTemp, *pProj, *pQ, *pR0;
    cudaGetSymbolAddress((void**)&pXr, g_Xr);
    cudaGetSymbolAddress((void**)&pXw, g_Xw);
    cudaGetSymbolAddress((void**)&pEcat, g_Ecat);
    cudaGetSymbolAddress((void**)&pWih, g_Wih);
    cudaGetSymbolAddress((void**)&pWlin, g_Wlin);
    cudaGetSymbolAddress((void**)&pFcat, g_Fcat);
    cudaGetSymbolAddress((void**)&pBiasz, g_biasz);
    cudaGetSymbolAddress((void**)&pXproj, g_xproj);
    cudaGetSymbolAddress((void**)&pTemp, g_temp);
    cudaGetSymbolAddress((void**)&pProj, g_proj);
    cudaGetSymbolAddress((void**)&pQ, g_q);
    cudaGetSymbolAddress((void**)&pR0, g_r0);

    k_init<<<4, 256>>>(b_ih, b_hh);
    k_softmax<<<256, 256>>>(dis);
    k_prep<<<16384, 256>>>((const float4*)X, (const float4*)E1, (const float4*)E2,
                           (const float4*)W_ih, (const float4*)W_hh, (const float4*)W_lin);

    // Fcat[j,0:256]=Wih[:,0:256]@E1^T ; Fcat[j,256:512]=Wih[:,256:512]@E2^T  (rounded)
    kg<0, 0, 0, 0, 1><<<dim3(8, 2, 2), 128, GSMEM>>>(
        pWih, nullptr, 256, 512, pEcat, 65536, 256,
        pFcat, 256, 512, nullptr, nullptr, nullptr, 256);

    // xproj = [Xr | Xw] @ Fcat^T + biasz  (K=512), per (b,l)
    kg<0, 0, 1, 1, 0><<<dim3(2, 8, 256), 128, GSMEM>>>(
        pXr, pXw, 65536, 256, pFcat, 0, 512,
        pXproj, 262144, 1024, pBiasz, nullptr, nullptr, 512);

    // persistent LSTM (+BN stats)
    k_lstm<<<128, 256, LSMEM>>>();

    k_finalize<<<1, 256>>>(gamma, beta);

    // proj = cvt(affine(temp)) @ Wlin^T + b_lin   (output rounded)
    kg<1, 0, 0, 1, 1><<<dim3(2, 2, 256), 128, GSMEM>>>(
        pTemp, nullptr, 65536, 256, pWlin, 0, 256,
        pProj, 65536, 256, b_lin, pQ, pR0, 256);

    // out = proj @ cvt(affine(temp))^T
    kg<0, 1, 0, 0, 0><<<dim3(2, 2, 256), 128, GSMEM>>>(
        pProj, nullptr, 65536, 256, pTemp, 65536, 256,
        out, 65536, 256, nullptr, pQ, pR0, 256);
}

// round 6
// speedup vs baseline: 2.1142x; 1.4810x over previous
#include <cuda_runtime.h>
#include <cuda_fp16.h>
#include <cstdint>
#include <math.h>

#define Bd 8
#define Ld 32
#define HN ((size_t)Bd * Ld * 256 * 256)   // 16777216

// ---------------- device scratch ------------------------------------------
__device__ __align__(16) float g_w[256 * 256];
__device__ __align__(16) __half g_Xh[HN];
__device__ __align__(16) __half g_Xwh[HN];
__device__ __align__(16) __half g_Ech[2 * 256 * 256];
__device__ __align__(16) __half g_Wihh[1024 * 512];
__device__ __align__(16) __half g_Wlinh[256 * 256];
__device__ __align__(16) __half g_Whrh[1024 * 256];
__device__ __align__(16) __half g_Fch[1024 * 512];
__device__ __align__(16) __half g_th[HN];     // LSTM h (rounded)
__device__ __align__(16) __half g_tbh[HN];    // batchnormed h
__device__ __align__(16) __half g_prh[HN];    // proj
__device__ __align__(16) float g_biasz[1024];
__device__ __align__(16) float g_xproj[HN * 4];
__device__ double g_sum[256], g_ssum[256];
__device__ float g_q[256], g_r0[256];
__device__ unsigned g_barcnt;
__device__ volatile unsigned g_bargen;

// ---------------- helpers --------------------------------------------------
__device__ __forceinline__ uint32_t pack2(float a, float b) {
    __half2 h = __floats2half2_rn(a, b);
    return *(uint32_t*)&h;
}
__device__ __forceinline__ void mma_f16(float* d, const uint32_t* a, const uint32_t* b) {
    asm volatile(
        "mma.sync.aligned.m16n8k16.row.col.f32.f16.f16.f32 "
        "{%0,%1,%2,%3}, {%4,%5,%6,%7}, {%8,%9}, {%0,%1,%2,%3};\n"
        : "+f"(d[0]), "+f"(d[1]), "+f"(d[2]), "+f"(d[3])
        : "r"(a[0]), "r"(a[1]), "r"(a[2]), "r"(a[3]), "r"(b[0]), "r"(b[1]));
}
__device__ __forceinline__ float sigf(float x) { return 1.f / (1.f + expf(-x)); }

__device__ __forceinline__ void cp16(uint32_t s, const void* g) {
    asm volatile("cp.async.cg.shared.global [%0], [%1], 16;" :: "r"(s), "l"(g));
}
#define CPCOMMIT asm volatile("cp.async.commit_group;")
#define CPWAIT1 asm volatile("cp.async.wait_group 1;")
#define CPWAIT0 asm volatile("cp.async.wait_group 0;")

// ---------------- init ------------------------------------------------------
__global__ void k_init(const float* __restrict__ bih, const float* __restrict__ bhh) {
    int i = blockIdx.x * 256 + threadIdx.x;  // grid 4
    g_biasz[i] = bih[i] + bhh[i];
    if (i < 256) { g_sum[i] = 0.0; g_ssum[i] = 0.0; }
    if (i == 0) { g_barcnt = 0; g_bargen = 0; }
}

// ---------------- softmax of -dis, row-wise ---------------------------------
__global__ void k_softmax(const float* __restrict__ dis) {
    __shared__ float red[256];
    int o = blockIdx.x, t = threadIdx.x;
    float e = expf(-dis[o * 256 + t]);
    red[t] = e;
    __syncthreads();
    for (int s = 128; s > 0; s >>= 1) {
        if (t < s) red[t] += red[t + s];
        __syncthreads();
    }
    g_w[o * 256 + t] = e / red[0];
}

// ---------------- prep: fp16 operand copies ---------------------------------
__global__ void k_prep(const float4* __restrict__ X, const float4* __restrict__ E1,
                       const float4* __restrict__ E2, const float4* __restrict__ W_ih,
                       const float4* __restrict__ W_hh, const float4* __restrict__ W_lin) {
    long i = (long)blockIdx.x * 256 + threadIdx.x;  // grid 16384
    int nd = (int)(i & 16383);
    float4 x = X[i];
    float4 w = ((const float4*)g_w)[nd];
    ((uint2*)g_Xh)[i] = make_uint2(pack2(x.x, x.y), pack2(x.z, x.w));
    ((uint2*)g_Xwh)[i] = make_uint2(pack2(x.x * w.x, x.y * w.y), pack2(x.z * w.z, x.w * w.w));
    if (i < 32768) {
        float4 e = (i < 16384) ? E1[i] : E2[i - 16384];
        ((uint2*)g_Ech)[i] = make_uint2(pack2(e.x, e.y), pack2(e.z, e.w));
    }
    if (i < 131072) {
        float4 v = W_ih[i];
        ((uint2*)g_Wihh)[i] = make_uint2(pack2(v.x, v.y), pack2(v.z, v.w));
    }
    if (i < 65536) {
        float4 v = W_hh[i];
        ((uint2*)g_Whrh)[i] = make_uint2(pack2(v.x, v.y), pack2(v.z, v.w));
    }
    if (i < 16384) {
        float4 v = W_lin[i];
        ((uint2*)g_Wlinh)[i] = make_uint2(pack2(v.x, v.y), pack2(v.z, v.w));
    }
}

// ---------------- tb = half(q*h + r0) ----------------------------------------
__global__ void k_affine() {
    long i = (long)blockIdx.x * 256 + threadIdx.x;  // grid 32768 -> 8.39M half2
    uint32_t u = ((const uint32_t*)g_th)[i];
    __half2 h2 = *(__half2*)&u;
    float2 f = __half22float2(h2);
    int c = (int)((i * 2) & 255);
    f.x = f.x * g_q[c] + g_r0[c];
    f.y = f.y * g_q[c + 1] + g_r0[c + 1];
    ((uint32_t*)g_tbh)[i] = pack2(f.x, f.y);
}

// ---------------- 128x128 fp16 GEMM, 128 threads, 64x64 warp tile -----------
// C = A' @ Bt^T (+bias). AHALF: k>=256 reads A2. HB: +bias[col].
// OH: C is __half (packed half2 stores); else fp32.
template <int AHALF, int HB, int OH>
__global__ void __launch_bounds__(128, 2) kh(
    const __half* __restrict__ A, const __half* __restrict__ A2, long sA, int lda,
    const __half* __restrict__ Bt, long sB, int ldb,
    void* __restrict__ C, long sC, int ldc,
    const float* __restrict__ bias, int K) {
    extern __shared__ uint32_t smu[];   // 2 stages x (A 128x36 + B 128x36) u32

    const int tid = threadIdx.x;
    const int z = blockIdx.z;
    const __half* Ab = A + sA * z;
    const __half* Ab2 = AHALF ? (A2 + sA * z) : nullptr;
    const __half* Bb = Bt + sB * z;
    float* Cf = OH ? nullptr : ((float*)C + sC * z);
    __half* Ch = OH ? ((__half*)C + sC * z) : nullptr;
    const int row0 = blockIdx.x * 128, col0 = blockIdx.y * 128;

    const int lane = tid & 31, wid = tid >> 5;      // 4 warps
    const int wm = (wid >> 1) * 64, wn = (wid & 1) * 64;
    const int g = lane >> 2, tq = lane & 3;
    const int rL = tid >> 3, sg4 = (tid & 7) * 4, c8 = (tid & 7) * 8;
    const int nk = K / 64;
    const int STG = 2 * 128 * 36;   // u32 per stage

    auto load = [&](int s, int k0) {
        const __half* Asrc;
        int kc;
        if (AHALF && k0 >= 256) { Asrc = Ab2; kc = k0 - 256 + c8; }
        else { Asrc = Ab; kc = k0 + c8; }
        uint32_t ab = (uint32_t)__cvta_generic_to_shared(smu + s * STG);
        uint32_t bb = ab + 128 * 36 * 4;
#pragma unroll
        for (int i = 0; i < 8; i++) {
            int r = rL + i * 16;
            cp16(ab + (r * 36 + sg4) * 4, Asrc + (long)(row0 + r) * lda + kc);
        }
#pragma unroll
        for (int i = 0; i < 8; i++) {
            int r = rL + i * 16;
            cp16(bb + (r * 36 + sg4) * 4, Bb + (long)(col0 + r) * ldb + k0 + c8);
        }
        CPCOMMIT;
    };

    float acc[4][8][4] = {};
    load(0, 0);
    load(1, 64);
    for (int kt = 0; kt < nk; kt++) {
        if (kt + 1 < nk) { CPWAIT1; } else { CPWAIT0; }
        __syncthreads();
        const uint32_t* asu = smu + (kt & 1) * STG;
        const uint32_t* bsu = asu + 128 * 36;
#pragma unroll
        for (int kw = 0; kw < 32; kw += 8) {      // 4 K16 groups per chunk
            uint32_t af[4][4], bf[8][2];
#pragma unroll
            for (int mi = 0; mi < 4; mi++) {
                int base = (wm + mi * 16 + g) * 36 + kw + tq;
                af[mi][0] = asu[base];       af[mi][1] = asu[base + 36 * 8];
                af[mi][2] = asu[base + 4];   af[mi][3] = asu[base + 36 * 8 + 4];
            }
#pragma unroll
            for (int ni = 0; ni < 8; ni++) {
                int base = (wn + ni * 8 + g) * 36 + kw + tq;
                bf[ni][0] = bsu[base];
                bf[ni][1] = bsu[base + 4];
            }
#pragma unroll
            for (int mi = 0; mi < 4; mi++)
#pragma unroll
                for (int ni = 0; ni < 8; ni++) mma_f16(acc[mi][ni], af[mi], bf[ni]);
        }
        __syncthreads();
        if (kt + 2 < nk) load(kt & 1, (kt + 2) * 64);
    }
#pragma unroll
    for (int mi = 0; mi < 4; mi++) {
        int rr = row0 + wm + mi * 16 + g;
#pragma unroll
        for (int ni = 0; ni < 8; ni++) {
            int cc = col0 + wn + ni * 8 + tq * 2;
            float b0 = HB ? bias[cc] : 0.f, b1 = HB ? bias[cc + 1] : 0.f;
            float v0 = acc[mi][ni][0] + b0, v1 = acc[mi][ni][1] + b1;
            float v2 = acc[mi][ni][2] + b0, v3 = acc[mi][ni][3] + b1;
            if (OH) {
                *(uint32_t*)&Ch[(long)rr * ldc + cc] = pack2(v0, v1);
                *(uint32_t*)&Ch[(long)(rr + 8) * ldc + cc] = pack2(v2, v3);
            } else {
                Cf[(long)rr * ldc + cc] = v0;
                Cf[(long)rr * ldc + cc + 1] = v1;
                Cf[(long)(rr + 8) * ldc + cc] = v2;
                Cf[(long)(rr + 8) * ldc + cc + 1] = v3;
            }
        }
    }
}

// ---------------- grid barrier ----------------------------------------------
__device__ __forceinline__ void gridbar(unsigned nb, unsigned& mygen) {
    __syncthreads();
    if (threadIdx.x == 0) {
        __threadfence();
        unsigned old = atomicAdd(&g_barcnt, 1u);
        if (old == nb - 1) {
            g_barcnt = 0;
            __threadfence();
            atomicAdd((unsigned*)&g_bargen, 1u);
        } else {
            while (g_bargen <= mygen) {}
        }
        __threadfence();
    }
    __syncthreads();
    mygen++;
}

// ---------------- persistent fused LSTM (fp16 GEMM) --------------------------
__global__ void __launch_bounds__(256, 1) k_lstm() {
    extern __shared__ uint32_t smL[];
    uint32_t* As = smL;                       // 2*64*36 u32
    uint32_t* Bs = smL + 2 * 64 * 36;         // 2*256*36 u32
    float* Zs = (float*)(smL + 2 * 64 * 36 + 2 * 256 * 36);   // 64*260
    float* Xp = Zs + 64 * 260;                                // 64*256

    const int tid = threadIdx.x;
    const int bid = blockIdx.x;
    const int rows0 = (bid >> 2) * 64, m0 = (bid & 3) * 64;
    const int b = rows0 >> 8, n0 = rows0 & 255;
    const int lane = tid & 31, wid = tid >> 5;
    const int wm = (wid >> 2) * 32, wn = (wid & 3) * 64;
    const int g = lane >> 2, tq = lane & 3;
    const int ml = tid & 63, rg = tid >> 6;

    float creg[16];
#pragma unroll
    for (int i = 0; i < 16; i++) creg[i] = 0.f;
    double sd = 0.0, ssd = 0.0;
    unsigned mygen = 0;

    const uint32_t xb = (uint32_t)__cvta_generic_to_shared(Xp);

    for (int t = 0; t < Ld; t++) {
        const long xz = ((long)b * Ld + t) * 256;
        {
#pragma unroll
            for (int k = 0; k < 16; k++) {
                int c = tid + k * 256;
                int row = c >> 6;
                int col4 = (c & 63) * 4;
                int gate = col4 >> 6, mcol = col4 & 63;
                cp16(xb + (row * 256 + col4) * 4,
                     g_xproj + (xz + n0 + row) * 1024 + gate * 256 + m0 + mcol);
            }
            CPCOMMIT;
        }

        float acc[2][8][4] = {};
        if (t > 0) {
            const __half* Ab = g_th + (((long)b * Ld + (t - 1)) * 256 + n0) * 256;
            auto load = [&](int stg, int k0) {
                uint32_t ab = (uint32_t)__cvta_generic_to_shared(As + stg * 64 * 36);
                uint32_t bb = (uint32_t)__cvta_generic_to_shared(Bs + stg * 256 * 36);
#pragma unroll
                for (int i = 0; i < 2; i++) {
                    int idx = tid + i * 256;
                    int r = idx >> 3, sgh = idx & 7;
                    cp16(ab + (r * 36 + sgh * 4) * 4, Ab + (long)r * 256 + k0 + sgh * 8);
                }
#pragma unroll
                for (int i = 0; i < 8; i++) {
                    int idx = tid + i * 256;
                    int ng = idx >> 3, sgh = idx & 7;
                    int wrow = (ng >> 6) * 256 + m0 + (ng & 63);
                    cp16(bb + (ng * 36 + sgh * 4) * 4, g_Whrh + (long)wrow * 256 + k0 + sgh * 8);
                }
                CPCOMMIT;
            };
            load(0, 0);
            for (int kt = 0; kt < 4; kt++) {     // K=256 halves, chunks of 64
                if (kt < 3) { load((kt + 1) & 1, (kt + 1) * 64); CPWAIT1; }
                else { CPWAIT0; }
                __syncthreads();
                const uint32_t* as = As + (kt & 1) * 64 * 36;
                const uint32_t* bs = Bs + (kt & 1) * 256 * 36;
#pragma unroll
                for (int kw = 0; kw < 32; kw += 8) {
                    uint32_t af[2][4], bf[8][2];
#pragma unroll
                    for (int mi = 0; mi < 2; mi++) {
                        int base = (wm + mi * 16 + g) * 36 + kw + tq;
                        af[mi][0] = as[base];     af[mi][1] = as[base + 36 * 8];
                        af[mi][2] = as[base + 4]; af[mi][3] = as[base + 36 * 8 + 4];
                    }
#pragma unroll
                    for (int ni = 0; ni < 8; ni++) {
                        int base = (wn + ni * 8 + g) * 36 + kw + tq;
                        bf[ni][0] = bs[base]; bf[ni][1] = bs[base + 4];
                    }
#pragma unroll
                    for (int mi = 0; mi < 2; mi++)
#pragma unroll
                        for (int ni = 0; ni < 8; ni++) mma_f16(acc[mi][ni], af[mi], bf[ni]);
                }
                __syncthreads();
            }
        } else {
            CPWAIT0;
            __syncthreads();
        }

#pragma unroll
        for (int mi = 0; mi < 2; mi++) {
            int zr = wm + mi * 16 + g;
#pragma unroll
            for (int ni = 0; ni < 8; ni++) {
                int zc = wn + ni * 8 + tq * 2;
                Zs[zr * 260 + zc] = acc[mi][ni][0];
                Zs[zr * 260 + zc + 1] = acc[mi][ni][1];
                Zs[(zr + 8) * 260 + zc] = acc[mi][ni][2];
                Zs[(zr + 8) * 260 + zc + 1] = acc[mi][ni][3];
            }
        }
        __syncthreads();

        float ps = 0.f, pss = 0.f;
#pragma unroll 4
        for (int i = 0; i < 16; i++) {
            int r = rg * 16 + i;
            int nn = n0 + r;
            float zi = Zs[r * 260 + ml] + Xp[r * 256 + ml];
            float zf = Zs[r * 260 + 64 + ml] + Xp[r * 256 + 64 + ml];
            float zg = Zs[r * 260 + 128 + ml] + Xp[r * 256 + 128 + ml];
            float zo = Zs[r * 260 + 192 + ml] + Xp[r * 256 + 192 + ml];
            float ig = sigf(zi), fg = sigf(zf), gg = tanhf(zg), og = sigf(zo);
            float c = fg * creg[i] + ig * gg;
            creg[i] = c;
            __half hh = __float2half_rn(og * tanhf(c));
            g_th[(xz + nn) * 256 + m0 + ml] = hh;
            float h = __half2float(hh);
            ps += h; pss += h * h;
        }
        sd += (double)ps; ssd += (double)pss;

        if (t < Ld - 1) gridbar(128, mygen);
    }
    atomicAdd(&g_sum[m0 + ml], sd);
    atomicAdd(&g_ssum[m0 + ml], ssd);
}

// ---------------- BN finalize -------------------------------------------------
__global__ void k_finalize(const float* __restrict__ gamma, const float* __restrict__ beta) {
    int m = threadIdx.x;
    double mu = g_sum[m] / 65536.0;
    double var = g_ssum[m] / 65536.0 - mu * mu;
    float q = gamma[m] * (float)(1.0 / sqrt(var + 1e-5));
    g_q[m] = q;
    g_r0[m] = beta[m] - (float)mu * q;
}

// ---------------- launch ------------------------------------------------------
extern "C" void kernel_launch(void* const* d_in, const int* in_sizes, int n_in,
                              void* d_out, int out_size) {
    const float* X     = (const float*)d_in[0];
    const float* dis   = (const float*)d_in[1];
    const float* E1    = (const float*)d_in[2];
    const float* E2    = (const float*)d_in[3];
    const float* W_ih  = (const float*)d_in[4];
    const float* W_hh  = (const float*)d_in[5];
    const float* b_ih  = (const float*)d_in[6];
    const float* b_hh  = (const float*)d_in[7];
    const float* gamma = (const float*)d_in[8];
    const float* beta  = (const float*)d_in[9];
    const float* W_lin = (const float*)d_in[10];
    const float* b_lin = (const float*)d_in[11];
    float* out = (float*)d_out;

    const int GSMEM = 2 * 2 * 128 * 36 * 4;   // 73728 B
    const int LSMEM = (2 * 64 * 36 + 2 * 256 * 36 + 64 * 260 + 64 * 256) * 4;

    cudaFuncSetAttribute(kh<0, 0, 1>, cudaFuncAttributeMaxDynamicSharedMemorySize, GSMEM);
    cudaFuncSetAttribute(kh<1, 1, 0>, cudaFuncAttributeMaxDynamicSharedMemorySize, GSMEM);
    cudaFuncSetAttribute(kh<0, 1, 1>, cudaFuncAttributeMaxDynamicSharedMemorySize, GSMEM);
    cudaFuncSetAttribute(kh<0, 0, 0>, cudaFuncAttributeMaxDynamicSharedMemorySize, GSMEM);
    cudaFuncSetAttribute(k_lstm, cudaFuncAttributeMaxDynamicSharedMemorySize, LSMEM);

    __half *pXh, *pXwh, *pEch, *pWihh, *pWlinh, *pFch, *pTh, *pTbh, *pPrh;
    float *pBiasz, *pXproj;
    cudaGetSymbolAddress((void**)&pXh, g_Xh);
    cudaGetSymbolAddress((void**)&pXwh, g_Xwh);
    cudaGetSymbolAddress((void**)&pEch, g_Ech);
    cudaGetSymbolAddress((void**)&pWihh, g_Wihh);
    cudaGetSymbolAddress((void**)&pWlinh, g_Wlinh);
    cudaGetSymbolAddress((void**)&pFch, g_Fch);
    cudaGetSymbolAddress((void**)&pTh, g_th);
    cudaGetSymbolAddress((void**)&pTbh, g_tbh);
    cudaGetSymbolAddress((void**)&pPrh, g_prh);
    cudaGetSymbolAddress((void**)&pBiasz, g_biasz);
    cudaGetSymbolAddress((void**)&pXproj, g_xproj);

    k_init<<<4, 256>>>(b_ih, b_hh);
    k_softmax<<<256, 256>>>(dis);
    k_prep<<<16384, 256>>>((const float4*)X, (const float4*)E1, (const float4*)E2,
                           (const float4*)W_ih, (const float4*)W_hh, (const float4*)W_lin);

    // Fcat[j,0:256]=Wih[:,0:256]@E1^T ; Fcat[j,256:512]=Wih[:,256:512]@E2^T
    kh<0, 0, 1><<<dim3(8, 2, 2), 128, GSMEM>>>(
        pWihh, nullptr, 256, 512, pEch, 65536, 256,
        pFch, 256, 512, nullptr, 256);

    // xproj = [Xh | Xwh] @ Fcat^T + biasz  (K=512), per (b,l), fp32 out
    kh<1, 1, 0><<<dim3(2, 8, 256), 128, GSMEM>>>(
        pXh, pXwh, 65536, 256, pFch, 0, 512,
        pXproj, 262144, 1024, pBiasz, 512);

    // persistent LSTM (+BN stats)
    k_lstm<<<128, 256, LSMEM>>>();

    k_finalize<<<1, 256>>>(gamma, beta);
    k_affine<<<32768, 256>>>();

    // proj = tb @ Wlin^T + b_lin  (half out)
    kh<0, 1, 1><<<dim3(2, 2, 256), 128, GSMEM>>>(
        pTbh, nullptr, 65536, 256, pWlinh, 0, 256,
        pPrh, 65536, 256, b_lin, 256);

    // out = proj @ tb^T  (fp32 out)
    kh<0, 0, 0><<<dim3(2, 2, 256), 128, GSMEM>>>(
        pPrh, nullptr, 65536, 256, pTbh, 65536, 256,
        out, 65536, 256, nullptr, 256);
}

// round 7
// speedup vs baseline: 2.3247x; 1.0995x over previous
#include <cuda_runtime.h>
#include <cuda_fp16.h>
#include <cstdint>
#include <math.h>

#define Bd 8
#define Ld 32
#define HN ((size_t)Bd * Ld * 256 * 256)   // 16777216

// ---------------- device scratch ------------------------------------------
__device__ __align__(16) float g_w[256 * 256];
__device__ __align__(16) __half g_Xh[HN];
__device__ __align__(16) __half g_Xwh[HN];
__device__ __align__(16) __half g_Ech[2 * 256 * 256];
__device__ __align__(16) __half g_Wihh[1024 * 512];
__device__ __align__(16) __half g_Wlinh[256 * 256];
__device__ __align__(16) __half g_Whrh[1024 * 256];
__device__ __align__(16) __half g_Fch[1024 * 512];
__device__ __align__(16) __half g_th[HN];     // LSTM h
__device__ __align__(16) __half g_tbh[HN];    // batchnormed h
__device__ __align__(16) __half g_prh[HN];    // proj
__device__ __align__(16) float g_biasz[1024];
__device__ __align__(16) float g_xproj[HN * 4];
__device__ double g_sum[256], g_ssum[256];
__device__ float g_q[256], g_r0[256];
__device__ unsigned g_barcnt;
__device__ volatile unsigned g_bargen;

// ---------------- helpers --------------------------------------------------
__device__ __forceinline__ uint32_t pack2(float a, float b) {
    __half2 h = __floats2half2_rn(a, b);
    return *(uint32_t*)&h;
}
__device__ __forceinline__ void mma_f16(float* d, const uint32_t* a, const uint32_t* b) {
    asm volatile(
        "mma.sync.aligned.m16n8k16.row.col.f32.f16.f16.f32 "
        "{%0,%1,%2,%3}, {%4,%5,%6,%7}, {%8,%9}, {%0,%1,%2,%3};\n"
        : "+f"(d[0]), "+f"(d[1]), "+f"(d[2]), "+f"(d[3])
        : "r"(a[0]), "r"(a[1]), "r"(a[2]), "r"(a[3]), "r"(b[0]), "r"(b[1]));
}
__device__ __forceinline__ float sigf(float x) { return 1.f / (1.f + expf(-x)); }

__device__ __forceinline__ void cp16(uint32_t s, const void* g) {
    asm volatile("cp.async.cg.shared.global [%0], [%1], 16;" :: "r"(s), "l"(g));
}
#define CPCOMMIT asm volatile("cp.async.commit_group;")
#define CPWAITG1 asm volatile("cp.async.wait_group 1;")
#define CPWAIT1 asm volatile("cp.async.wait_group 1;")
#define CPWAIT0 asm volatile("cp.async.wait_group 0;")

// ---------------- init ------------------------------------------------------
__global__ void k_init(const float* __restrict__ bih, const float* __restrict__ bhh) {
    int i = blockIdx.x * 256 + threadIdx.x;  // grid 4
    g_biasz[i] = bih[i] + bhh[i];
    if (i < 256) { g_sum[i] = 0.0; g_ssum[i] = 0.0; }
    if (i == 0) { g_barcnt = 0; g_bargen = 0; }
}

// ---------------- softmax of -dis, row-wise ---------------------------------
__global__ void k_softmax(const float* __restrict__ dis) {
    __shared__ float red[256];
    int o = blockIdx.x, t = threadIdx.x;
    float e = expf(-dis[o * 256 + t]);
    red[t] = e;
    __syncthreads();
    for (int s = 128; s > 0; s >>= 1) {
        if (t < s) red[t] += red[t + s];
        __syncthreads();
    }
    g_w[o * 256 + t] = e / red[0];
}

// ---------------- prep: fp16 operand copies ---------------------------------
__global__ void k_prep(const float4* __restrict__ X, const float4* __restrict__ E1,
                       const float4* __restrict__ E2, const float4* __restrict__ W_ih,
                       const float4* __restrict__ W_hh, const float4* __restrict__ W_lin) {
    long i = (long)blockIdx.x * 256 + threadIdx.x;  // grid 16384
    int nd = (int)(i & 16383);
    float4 x = X[i];
    float4 w = ((const float4*)g_w)[nd];
    ((uint2*)g_Xh)[i] = make_uint2(pack2(x.x, x.y), pack2(x.z, x.w));
    ((uint2*)g_Xwh)[i] = make_uint2(pack2(x.x * w.x, x.y * w.y), pack2(x.z * w.z, x.w * w.w));
    if (i < 32768) {
        float4 e = (i < 16384) ? E1[i] : E2[i - 16384];
        ((uint2*)g_Ech)[i] = make_uint2(pack2(e.x, e.y), pack2(e.z, e.w));
    }
    if (i < 131072) {
        float4 v = W_ih[i];
        ((uint2*)g_Wihh)[i] = make_uint2(pack2(v.x, v.y), pack2(v.z, v.w));
    }
    if (i < 65536) {
        float4 v = W_hh[i];
        ((uint2*)g_Whrh)[i] = make_uint2(pack2(v.x, v.y), pack2(v.z, v.w));
    }
    if (i < 16384) {
        float4 v = W_lin[i];
        ((uint2*)g_Wlinh)[i] = make_uint2(pack2(v.x, v.y), pack2(v.z, v.w));
    }
}

// ---------------- tb = half(q*h + r0) ----------------------------------------
__global__ void k_affine() {
    long i = (long)blockIdx.x * 256 + threadIdx.x;  // grid 32768
    uint32_t u = ((const uint32_t*)g_th)[i];
    __half2 h2 = *(__half2*)&u;
    float2 f = __half22float2(h2);
    int c = (int)((i * 2) & 255);
    f.x = f.x * g_q[c] + g_r0[c];
    f.y = f.y * g_q[c + 1] + g_r0[c + 1];
    ((uint32_t*)g_tbh)[i] = pack2(f.x, f.y);
}

// ---------------- 128x128 fp16 GEMM (unchanged from R5) ----------------------
template <int AHALF, int HB, int OH>
__global__ void __launch_bounds__(128, 2) kh(
    const __half* __restrict__ A, const __half* __restrict__ A2, long sA, int lda,
    const __half* __restrict__ Bt, long sB, int ldb,
    void* __restrict__ C, long sC, int ldc,
    const float* __restrict__ bias, int K) {
    extern __shared__ uint32_t smu[];

    const int tid = threadIdx.x;
    const int z = blockIdx.z;
    const __half* Ab = A + sA * z;
    const __half* Ab2 = AHALF ? (A2 + sA * z) : nullptr;
    const __half* Bb = Bt + sB * z;
    float* Cf = OH ? nullptr : ((float*)C + sC * z);
    __half* Ch = OH ? ((__half*)C + sC * z) : nullptr;
    const int row0 = blockIdx.x * 128, col0 = blockIdx.y * 128;

    const int lane = tid & 31, wid = tid >> 5;
    const int wm = (wid >> 1) * 64, wn = (wid & 1) * 64;
    const int g = lane >> 2, tq = lane & 3;
    const int rL = tid >> 3, sg4 = (tid & 7) * 4, c8 = (tid & 7) * 8;
    const int nk = K / 64;
    const int STG = 2 * 128 * 36;

    auto load = [&](int s, int k0) {
        const __half* Asrc;
        int kc;
        if (AHALF && k0 >= 256) { Asrc = Ab2; kc = k0 - 256 + c8; }
        else { Asrc = Ab; kc = k0 + c8; }
        uint32_t ab = (uint32_t)__cvta_generic_to_shared(smu + s * STG);
        uint32_t bb = ab + 128 * 36 * 4;
#pragma unroll
        for (int i = 0; i < 8; i++) {
            int r = rL + i * 16;
            cp16(ab + (r * 36 + sg4) * 4, Asrc + (long)(row0 + r) * lda + kc);
        }
#pragma unroll
        for (int i = 0; i < 8; i++) {
            int r = rL + i * 16;
            cp16(bb + (r * 36 + sg4) * 4, Bb + (long)(col0 + r) * ldb + k0 + c8);
        }
        CPCOMMIT;
    };

    float acc[4][8][4] = {};
    load(0, 0);
    load(1, 64);
    for (int kt = 0; kt < nk; kt++) {
        if (kt + 1 < nk) { CPWAIT1; } else { CPWAIT0; }
        __syncthreads();
        const uint32_t* asu = smu + (kt & 1) * STG;
        const uint32_t* bsu = asu + 128 * 36;
#pragma unroll
        for (int kw = 0; kw < 32; kw += 8) {
            uint32_t af[4][4], bf[8][2];
#pragma unroll
            for (int mi = 0; mi < 4; mi++) {
                int base = (wm + mi * 16 + g) * 36 + kw + tq;
                af[mi][0] = asu[base];       af[mi][1] = asu[base + 36 * 8];
                af[mi][2] = asu[base + 4];   af[mi][3] = asu[base + 36 * 8 + 4];
            }
#pragma unroll
            for (int ni = 0; ni < 8; ni++) {
                int base = (wn + ni * 8 + g) * 36 + kw + tq;
                bf[ni][0] = bsu[base];
                bf[ni][1] = bsu[base + 4];
            }
#pragma unroll
            for (int mi = 0; mi < 4; mi++)
#pragma unroll
                for (int ni = 0; ni < 8; ni++) mma_f16(acc[mi][ni], af[mi], bf[ni]);
        }
        __syncthreads();
        if (kt + 2 < nk) load(kt & 1, (kt + 2) * 64);
    }
#pragma unroll
    for (int mi = 0; mi < 4; mi++) {
        int rr = row0 + wm + mi * 16 + g;
#pragma unroll
        for (int ni = 0; ni < 8; ni++) {
            int cc = col0 + wn + ni * 8 + tq * 2;
            float b0 = HB ? bias[cc] : 0.f, b1 = HB ? bias[cc + 1] : 0.f;
            float v0 = acc[mi][ni][0] + b0, v1 = acc[mi][ni][1] + b1;
            float v2 = acc[mi][ni][2] + b0, v3 = acc[mi][ni][3] + b1;
            if (OH) {
                *(uint32_t*)&Ch[(long)rr * ldc + cc] = pack2(v0, v1);
                *(uint32_t*)&Ch[(long)(rr + 8) * ldc + cc] = pack2(v2, v3);
            } else {
                Cf[(long)rr * ldc + cc] = v0;
                Cf[(long)rr * ldc + cc + 1] = v1;
                Cf[(long)(rr + 8) * ldc + cc] = v2;
                Cf[(long)(rr + 8) * ldc + cc + 1] = v3;
            }
        }
    }
}

// ---------------- grid barrier ----------------------------------------------
__device__ __forceinline__ void gridbar(unsigned nb, unsigned& mygen) {
    __syncthreads();
    if (threadIdx.x == 0) {
        __threadfence();
        unsigned old = atomicAdd(&g_barcnt, 1u);
        if (old == nb - 1) {
            g_barcnt = 0;
            __threadfence();
            atomicAdd((unsigned*)&g_bargen, 1u);
        } else {
            while (g_bargen <= mygen) {}
        }
        __threadfence();
    }
    __syncthreads();
    mygen++;
}

// ---------------- persistent LSTM: resident Whh, gate-interleaved tiles ------
// grid 128 = 32 row-tiles(64) x 4 m-tiles(64). 256 thr = 4 M-warps x 2 N-warps.
// Warp N-tile = 128 cols, gate-interleaved: col c -> gate c>>5, msub c&31.
// D-fragment of a thread holds i,f,g,o for the same (row,m): no Z staging.
__global__ void __launch_bounds__(256, 1) k_lstm() {
    extern __shared__ uint32_t smL[];
    uint32_t* Bs = smL;                          // 256 x 128 u32 (swizzled)
    uint32_t* As = smL + 256 * 128;              // 64 x 128 u32 (swizzled)
    float* Xp = (float*)(smL + 256 * 128 + 64 * 128);  // 64 x 260 f32

    const int tid = threadIdx.x;
    const int bid = blockIdx.x;
    const int rows0 = (bid >> 2) * 64, m0 = (bid & 3) * 64;
    const int b = rows0 >> 8, n0 = rows0 & 255;
    const int lane = tid & 31, wid = tid >> 5;
    const int g = lane >> 2, tq = lane & 3;
    const int wr = (wid >> 1) * 16;              // warp row base (0..48)
    const int cbase = (wid & 1) * 128;           // warp col base in Bs
    const int r0 = wr + g, r1 = wr + g + 8;

    const uint32_t bsb = (uint32_t)__cvta_generic_to_shared(Bs);
    const uint32_t asb = (uint32_t)__cvta_generic_to_shared(As);
    const uint32_t xpb = (uint32_t)__cvta_generic_to_shared(Xp);

    // ---- preload gathered Whh slice (once) ----
#pragma unroll
    for (int w = 0; w < 32; w++) {
        int idx = tid + w * 256;
        int c = idx >> 5, s = idx & 31;
        int n = c & 127, nw = c >> 7;
        int wrow = (n >> 5) * 256 + m0 + nw * 32 + (n & 31);
        cp16(bsb + (c * 128 + ((s ^ (c & 7)) << 2)) * 4,
             g_Whrh + (long)wrow * 256 + s * 8);
    }
    CPCOMMIT; CPWAIT0;
    __syncthreads();

    float creg[16];
#pragma unroll
    for (int i = 0; i < 16; i++) creg[i] = 0.f;
    unsigned mygen = 0;

    for (int t = 0; t < Ld; t++) {
        const long xz = ((long)b * Ld + t) * 256;

        // A = h_{t-1} (swizzled); empty group at t=0
        if (t > 0) {
            const __half* Ab = g_th + (((long)b * Ld + (t - 1)) * 256 + n0) * 256;
#pragma unroll
            for (int w = 0; w < 8; w++) {
                int idx = tid + w * 256;
                int r = idx >> 5, s = idx & 31;
                cp16(asb + (r * 128 + ((s ^ (r & 7)) << 2)) * 4,
                     Ab + (long)r * 256 + s * 8);
            }
        }
        CPCOMMIT;
        // Xp slice (fp32): rows 64 x (4 gates x 64 m)
#pragma unroll
        for (int w = 0; w < 16; w++) {
            int idx = tid + w * 256;
            int r = idx >> 6, s = idx & 63;
            int gate = s >> 4, ms = (s & 15) * 4;
            cp16(xpb + (r * 260 + gate * 64 + ms) * 4,
                 g_xproj + (xz + n0 + r) * 1024 + gate * 256 + m0 + ms);
        }
        CPCOMMIT;
        CPWAITG1;             // A landed (Xp may still be in flight)
        __syncthreads();

        float acc[16][4] = {};
        if (t > 0) {
#pragma unroll
            for (int j = 0; j < 16; j++) {
                const int x0 = (((2 * j) ^ g) << 2) + tq;
                const int x1 = (((2 * j + 1) ^ g) << 2) + tq;
                uint32_t af[4];
                af[0] = As[r0 * 128 + x0];
                af[1] = As[r1 * 128 + x0];
                af[2] = As[r0 * 128 + x1];
                af[3] = As[r1 * 128 + x1];
#pragma unroll
                for (int ni = 0; ni < 16; ni++) {
                    int c = cbase + ni * 8 + g;
                    uint32_t bf[2];
                    bf[0] = Bs[c * 128 + x0];
                    bf[1] = Bs[c * 128 + x1];
                    mma_f16(acc[ni], af, bf);
                }
            }
        }
        CPWAIT0;              // Xp landed
        __syncthreads();

        // gates straight from registers (i,f,g,o = acc[ni2], [4+],[8+],[12+])
#pragma unroll
        for (int ni2 = 0; ni2 < 4; ni2++) {
            const int mloc = (wid & 1) * 32 + ni2 * 8 + tq * 2;
#pragma unroll
            for (int rs = 0; rs < 2; rs++) {
                const int lr = rs ? r1 : r0;
                const float* xr = Xp + lr * 260 + mloc;
                float hv[2];
#pragma unroll
                for (int col = 0; col < 2; col++) {
                    int ai = rs * 2 + col;
                    float zi = acc[ni2][ai] + xr[col];
                    float zf = acc[4 + ni2][ai] + xr[64 + col];
                    float zg = acc[8 + ni2][ai] + xr[128 + col];
                    float zo = acc[12 + ni2][ai] + xr[192 + col];
                    int k = ni2 * 4 + ai;
                    float cc = sigf(zf) * creg[k] + sigf(zi) * tanhf(zg);
                    creg[k] = cc;
                    hv[col] = sigf(zo) * tanhf(cc);
                }
                *(uint32_t*)&g_th[(xz + n0 + lr) * 256 + m0 + mloc] = pack2(hv[0], hv[1]);
            }
        }
        if (t < Ld - 1) gridbar(128, mygen);
    }
}

// ---------------- BN stats over g_th ------------------------------------------
__global__ void k_stats() {
    int m = threadIdx.x;
    long base = (long)blockIdx.x * 65536;    // grid 256 (b,l) slices
    float s = 0.f, ss = 0.f;
#pragma unroll 4
    for (int n = 0; n < 256; n++) {
        float v = __half2float(g_th[base + (long)n * 256 + m]);
        s += v; ss += v * v;
    }
    atomicAdd(&g_sum[m], (double)s);
    atomicAdd(&g_ssum[m], (double)ss);
}

// ---------------- BN finalize -------------------------------------------------
__global__ void k_finalize(const float* __restrict__ gamma, const float* __restrict__ beta) {
    int m = threadIdx.x;
    double mu = g_sum[m] / 65536.0;
    double var = g_ssum[m] / 65536.0 - mu * mu;
    float q = gamma[m] * (float)(1.0 / sqrt(var + 1e-5));
    g_q[m] = q;
    g_r0[m] = beta[m] - (float)mu * q;
}

// ---------------- launch ------------------------------------------------------
extern "C" void kernel_launch(void* const* d_in, const int* in_sizes, int n_in,
                              void* d_out, int out_size) {
    const float* X     = (const float*)d_in[0];
    const float* dis   = (const float*)d_in[1];
    const float* E1    = (const float*)d_in[2];
    const float* E2    = (const float*)d_in[3];
    const float* W_ih  = (const float*)d_in[4];
    const float* W_hh  = (const float*)d_in[5];
    const float* b_ih  = (const float*)d_in[6];
    const float* b_hh  = (const float*)d_in[7];
    const float* gamma = (const float*)d_in[8];
    const float* beta  = (const float*)d_in[9];
    const float* W_lin = (const float*)d_in[10];
    const float* b_lin = (const float*)d_in[11];
    float* out = (float*)d_out;

    const int GSMEM = 2 * 2 * 128 * 36 * 4;                       // 73728 B
    const int LSMEM = (256 * 128 + 64 * 128) * 4 + 64 * 260 * 4;  // 230400 B

    cudaFuncSetAttribute(kh<0, 0, 1>, cudaFuncAttributeMaxDynamicSharedMemorySize, GSMEM);
    cudaFuncSetAttribute(kh<1, 1, 0>, cudaFuncAttributeMaxDynamicSharedMemorySize, GSMEM);
    cudaFuncSetAttribute(kh<0, 1, 1>, cudaFuncAttributeMaxDynamicSharedMemorySize, GSMEM);
    cudaFuncSetAttribute(kh<0, 0, 0>, cudaFuncAttributeMaxDynamicSharedMemorySize, GSMEM);
    cudaFuncSetAttribute(k_lstm, cudaFuncAttributeMaxDynamicSharedMemorySize, LSMEM);

    __half *pXh, *pXwh, *pEch, *pWihh, *pWlinh, *pFch, *pTbh, *pPrh;
    float *pBiasz, *pXproj;
    cudaGetSymbolAddress((void**)&pXh, g_Xh);
    cudaGetSymbolAddress((void**)&pXwh, g_Xwh);
    cudaGetSymbolAddress((void**)&pEch, g_Ech);
    cudaGetSymbolAddress((void**)&pWihh, g_Wihh);
    cudaGetSymbolAddress((void**)&pWlinh, g_Wlinh);
    cudaGetSymbolAddress((void**)&pFch, g_Fch);
    cudaGetSymbolAddress((void**)&pTbh, g_tbh);
    cudaGetSymbolAddress((void**)&pPrh, g_prh);
    cudaGetSymbolAddress((void**)&pBiasz, g_biasz);
    cudaGetSymbolAddress((void**)&pXproj, g_xproj);

    k_init<<<4, 256>>>(b_ih, b_hh);
    k_softmax<<<256, 256>>>(dis);
    k_prep<<<16384, 256>>>((const float4*)X, (const float4*)E1, (const float4*)E2,
                           (const float4*)W_ih, (const float4*)W_hh, (const float4*)W_lin);

    // Fcat
    kh<0, 0, 1><<<dim3(8, 2, 2), 128, GSMEM>>>(
        pWihh, nullptr, 256, 512, pEch, 65536, 256,
        pFch, 256, 512, nullptr, 256);

    // xproj = [Xh | Xwh] @ Fcat^T + biasz (K=512), fp32 out
    kh<1, 1, 0><<<dim3(2, 8, 256), 128, GSMEM>>>(
        pXh, pXwh, 65536, 256, pFch, 0, 512,
        pXproj, 262144, 1024, pBiasz, 512);

    // persistent LSTM (resident Whh, register gates)
    k_lstm<<<128, 256, LSMEM>>>();

    k_stats<<<256, 256>>>();
    k_finalize<<<1, 256>>>(gamma, beta);
    k_affine<<<32768, 256>>>();

    // proj = tb @ Wlin^T + b_lin (half out)
    kh<0, 1, 1><<<dim3(2, 2, 256), 128, GSMEM>>>(
        pTbh, nullptr, 65536, 256, pWlinh, 0, 256,
        pPrh, 65536, 256, b_lin, 256);

    // out = proj @ tb^T (fp32 out)
    kh<0, 0, 0><<<dim3(2, 2, 256), 128, GSMEM>>>(
        pPrh, nullptr, 65536, 256, pTbh, 65536, 256,
        out, 65536, 256, nullptr, 256);
}